// round 1
// baseline (speedup 1.0000x reference)
#include <cuda_runtime.h>
#include <math.h>

// Problem constants (fixed by the dataset)
#define BATCH 2
#define TT    8
#define HH    16
#define WW    16
#define DMODEL 1024
#define NHEADS 16
#define NKV    4
#define HDIM   64
#define NTOK   2048              // TT*HH*WW
#define MROWS  4096              // BATCH*NTOK

// ---------------- scratch (device globals; no allocs allowed) ----------------
__device__ float g_qt[(size_t)BATCH * NHEADS * HDIM * NTOK]; // [b][h][d][n]
__device__ float g_kt[(size_t)BATCH * NKV    * HDIM * NTOK]; // [b][kv][d][n]
__device__ float g_vt[(size_t)BATCH * NKV    * NTOK * HDIM]; // [b][kv][n][d]
__device__ float g_o [(size_t)MROWS * DMODEL];               // [m][1024]

// =============================================================================
// Kernel 1: fused QKV GEMM + bias + RMSNorm + 3D RoPE + q-scale
//   C[4096 x 1536] tiles of 64x64; each 64-col tile == exactly one head.
// =============================================================================
__global__ __launch_bounds__(256) void qkv_kernel(
    const float* __restrict__ x,
    const float* __restrict__ Wq, const float* __restrict__ bq,
    const float* __restrict__ Wk, const float* __restrict__ bk,
    const float* __restrict__ Wv, const float* __restrict__ bv,
    const float* __restrict__ qn, const float* __restrict__ kn)
{
    __shared__ float As[16][68];   // [k][m]
    __shared__ float Bs[16][68];   // [k][n]
    __shared__ float ts[64][68];   // normalized tile for RoPE pairing

    const int tid = threadIdx.x;
    const int tx = tid & 15, ty = tid >> 4;
    const int m0   = blockIdx.y * 64;
    const int colb = blockIdx.x * 64;

    const float* Bmat; const float* bias; int ldb, seg, colloc;
    if (colb < 1024)      { Bmat = Wq; bias = bq; ldb = 1024; seg = 0; colloc = colb; }
    else if (colb < 1280) { Bmat = Wk; bias = bk; ldb = 256;  seg = 1; colloc = colb - 1024; }
    else                  { Bmat = Wv; bias = bv; ldb = 256;  seg = 2; colloc = colb - 1280; }

    float c[4][4] = {};
    const int arow = tid >> 2, ac = tid & 3;        // A tile loader
    const int brow = tid >> 4, bc = (tid & 15) * 4; // B tile loader

    for (int k0 = 0; k0 < 1024; k0 += 16) {
        float4 av = *(const float4*)&x[(size_t)(m0 + arow) * 1024 + k0 + ac * 4];
        As[ac*4+0][arow] = av.x; As[ac*4+1][arow] = av.y;
        As[ac*4+2][arow] = av.z; As[ac*4+3][arow] = av.w;
        *(float4*)&Bs[brow][bc] =
            *(const float4*)&Bmat[(size_t)(k0 + brow) * ldb + colloc + bc];
        __syncthreads();
        #pragma unroll
        for (int kk = 0; kk < 16; kk++) {
            float4 a = *(const float4*)&As[kk][ty * 4];
            float4 b = *(const float4*)&Bs[kk][tx * 4];
            float aa[4] = {a.x, a.y, a.z, a.w};
            float bb[4] = {b.x, b.y, b.z, b.w};
            #pragma unroll
            for (int i = 0; i < 4; i++)
                #pragma unroll
                for (int j = 0; j < 4; j++)
                    c[i][j] += aa[i] * bb[j];
        }
        __syncthreads();
    }

    // bias
    #pragma unroll
    for (int j = 0; j < 4; j++) {
        float bj = bias[colloc + tx * 4 + j];
        #pragma unroll
        for (int i = 0; i < 4; i++) c[i][j] += bj;
    }

    if (seg == 2) {
        // V: plain write to [b][kv][n][d]
        const int kv = colloc >> 6;
        #pragma unroll
        for (int i = 0; i < 4; i++) {
            int m = m0 + ty * 4 + i;
            int b = m >> 11, n = m & 2047;
            float4 o4 = make_float4(c[i][0], c[i][1], c[i][2], c[i][3]);
            *(float4*)&g_vt[(((size_t)(b * NKV + kv)) * NTOK + n) * HDIM + tx * 4] = o4;
        }
        return;
    }

    // ---- RMSNorm over head dim (the 64 cols of this tile) ----
    const float* nw = (seg == 0) ? qn : kn;
    float wj[4];
    #pragma unroll
    for (int j = 0; j < 4; j++) wj[j] = nw[tx * 4 + j];
    #pragma unroll
    for (int i = 0; i < 4; i++) {
        float ss = c[i][0]*c[i][0] + c[i][1]*c[i][1] + c[i][2]*c[i][2] + c[i][3]*c[i][3];
        ss += __shfl_xor_sync(0xffffffffu, ss, 1);
        ss += __shfl_xor_sync(0xffffffffu, ss, 2);
        ss += __shfl_xor_sync(0xffffffffu, ss, 4);
        ss += __shfl_xor_sync(0xffffffffu, ss, 8);
        float rstd = rsqrtf(ss * (1.0f / 64.0f) + 1e-6f);
        #pragma unroll
        for (int j = 0; j < 4; j++) c[i][j] = c[i][j] * rstd * wj[j];
    }
    #pragma unroll
    for (int i = 0; i < 4; i++)
        *(float4*)&ts[ty * 4 + i][tx * 4] = make_float4(c[i][0], c[i][1], c[i][2], c[i][3]);
    __syncthreads();

    // ---- factored 3D RoPE: dt=16 (t), dh=16 (h), dw=32 (w) ----
    int col_[4], po_[4], pk_[4]; float inv_[4]; bool low_[4];
    #pragma unroll
    for (int j = 0; j < 4; j++) {
        int col = tx * 4 + j; col_[j] = col;
        int jj, half, pk;
        if (col < 16)      { pk = 0; jj = col;      half = 8;  }
        else if (col < 32) { pk = 1; jj = col - 16; half = 8;  }
        else               { pk = 2; jj = col - 32; half = 16; }
        low_[j] = (jj < half);
        int f = low_[j] ? jj : jj - half;
        pk_[j] = pk;
        inv_[j] = __powf(10000.0f, -(float)f / (float)half);
        po_[j] = low_[j] ? col + half : col - half;
    }

    #pragma unroll
    for (int i = 0; i < 4; i++) {
        int r = ty * 4 + i;
        int m = m0 + r;
        int b = m >> 11, n = m & 2047;
        float pt = (float)(n >> 8);
        float ph = (float)((n >> 4) & 15);
        float pw = (float)(n & 15);
        #pragma unroll
        for (int j = 0; j < 4; j++) {
            float pos = (pk_[j] == 0) ? pt : (pk_[j] == 1 ? ph : pw);
            float ang = pos * inv_[j];
            float sv, cv;
            __sincosf(ang, &sv, &cv);
            float x0 = ts[r][col_[j]];
            float xp = ts[r][po_[j]];
            float o = low_[j] ? (x0 * cv - xp * sv) : (x0 * cv + xp * sv);
            if (seg == 0) {
                o *= 0.125f;  // HD^-0.5 score scale folded into q
                int h = colb >> 6;
                g_qt[(((size_t)(b * NHEADS + h)) * HDIM + col_[j]) * NTOK + n] = o;
            } else {
                int kv = colloc >> 6;
                g_kt[(((size_t)(b * NKV + kv)) * HDIM + col_[j]) * NTOK + n] = o;
            }
        }
    }
}

// =============================================================================
// Kernel 2: flash attention. 64 q-rows per block, 64-key tiles, online softmax.
//   q_s/k in [d][n] layout (pre-transposed in gmem); P via XOR-swizzled smem.
// =============================================================================
__global__ __launch_bounds__(256) void attn_kernel()
{
    __shared__ float q_s[64][64];    // [d][r]
    __shared__ float kv_s[64][64];   // K phase: [d][key]; V phase: [key][d]
    __shared__ float p_s[64 * 64];   // [key][r], XOR-swizzled

    const int tid = threadIdx.x;
    const int tx = tid & 15, ty = tid >> 4;
    const int q0 = blockIdx.x * 64;
    const int bh = blockIdx.y;
    const int b = bh >> 4, hq = bh & 15, kv = hq >> 2;

    const float* qbase = &g_qt[((size_t)(b * NHEADS + hq)) * HDIM * NTOK];
    const float* kbase = &g_kt[((size_t)(b * NKV + kv)) * HDIM * NTOK];
    const float* vbase = &g_vt[((size_t)(b * NKV + kv)) * NTOK * HDIM];

    const int ldrow = tid >> 4;        // 0..15
    const int ldcol = (tid & 15) * 4;  // 0..60

    // load Q tile (coalesced: q_t is [d][n])
    #pragma unroll
    for (int rep = 0; rep < 4; rep++) {
        int d = ldrow * 4 + rep;
        *(float4*)&q_s[d][ldcol] = *(const float4*)&qbase[(size_t)d * NTOK + q0 + ldcol];
    }

    float acc[4][4] = {};
    float mrow[4], lrow[4];
    #pragma unroll
    for (int i = 0; i < 4; i++) { mrow[i] = -1e30f; lrow[i] = 0.0f; }

    for (int kt = 0; kt < NTOK; kt += 64) {
        __syncthreads();  // prior iter's PV readers done with kv_s/p_s
        #pragma unroll
        for (int rep = 0; rep < 4; rep++) {
            int d = ldrow * 4 + rep;
            *(float4*)&kv_s[d][ldcol] = *(const float4*)&kbase[(size_t)d * NTOK + kt + ldcol];
        }
        __syncthreads();

        // S = Q^T K  (contraction over d)
        float s[4][4] = {};
        #pragma unroll 16
        for (int kk = 0; kk < 64; kk++) {
            float4 a = *(const float4*)&q_s[kk][ty * 4];
            float4 bb4 = *(const float4*)&kv_s[kk][tx * 4];
            float aa[4] = {a.x, a.y, a.z, a.w};
            float bb[4] = {bb4.x, bb4.y, bb4.z, bb4.w};
            #pragma unroll
            for (int i = 0; i < 4; i++)
                #pragma unroll
                for (int j = 0; j < 4; j++)
                    s[i][j] += aa[i] * bb[j];
        }

        // online softmax update
        #pragma unroll
        for (int i = 0; i < 4; i++) {
            float tm = fmaxf(fmaxf(s[i][0], s[i][1]), fmaxf(s[i][2], s[i][3]));
            tm = fmaxf(tm, __shfl_xor_sync(0xffffffffu, tm, 1));
            tm = fmaxf(tm, __shfl_xor_sync(0xffffffffu, tm, 2));
            tm = fmaxf(tm, __shfl_xor_sync(0xffffffffu, tm, 4));
            tm = fmaxf(tm, __shfl_xor_sync(0xffffffffu, tm, 8));
            float mn = fmaxf(mrow[i], tm);
            float corr = __expf(mrow[i] - mn);
            mrow[i] = mn;
            float rs = 0.0f;
            #pragma unroll
            for (int j = 0; j < 4; j++) { s[i][j] = __expf(s[i][j] - mn); rs += s[i][j]; }
            rs += __shfl_xor_sync(0xffffffffu, rs, 1);
            rs += __shfl_xor_sync(0xffffffffu, rs, 2);
            rs += __shfl_xor_sync(0xffffffffu, rs, 4);
            rs += __shfl_xor_sync(0xffffffffu, rs, 8);
            lrow[i] = lrow[i] * corr + rs;
            #pragma unroll
            for (int j = 0; j < 4; j++) acc[i][j] *= corr;
        }

        // store P transposed [key][r] with XOR swizzle (conflict-free)
        #pragma unroll
        for (int i = 0; i < 4; i++)
            #pragma unroll
            for (int j = 0; j < 4; j++) {
                int key = tx * 4 + j;
                int r   = ty * 4 + i;
                p_s[key * 64 + (r ^ (key & 31))] = s[i][j];
            }
        __syncthreads();  // S-phase readers of kv_s done; p_s complete

        // load V tile into kv_s as [key][d]
        #pragma unroll
        for (int rep = 0; rep < 4; rep++) {
            int key = ldrow * 4 + rep;
            *(float4*)&kv_s[key][ldcol] = *(const float4*)&vbase[(size_t)(kt + key) * HDIM + ldcol];
        }
        __syncthreads();

        // acc += P^T V  (contraction over key)
        #pragma unroll 16
        for (int kk = 0; kk < 64; kk++) {
            float a0 = p_s[kk * 64 + ((ty * 4 + 0) ^ (kk & 31))];
            float a1 = p_s[kk * 64 + ((ty * 4 + 1) ^ (kk & 31))];
            float a2 = p_s[kk * 64 + ((ty * 4 + 2) ^ (kk & 31))];
            float a3 = p_s[kk * 64 + ((ty * 4 + 3) ^ (kk & 31))];
            float4 bb4 = *(const float4*)&kv_s[kk][tx * 4];
            float bb[4] = {bb4.x, bb4.y, bb4.z, bb4.w};
            #pragma unroll
            for (int j = 0; j < 4; j++) {
                acc[0][j] += a0 * bb[j];
                acc[1][j] += a1 * bb[j];
                acc[2][j] += a2 * bb[j];
                acc[3][j] += a3 * bb[j];
            }
        }
    }

    // normalize + write O in [m][1024] layout
    #pragma unroll
    for (int i = 0; i < 4; i++) {
        float inv = 1.0f / lrow[i];
        int n = q0 + ty * 4 + i;
        float4 o4 = make_float4(acc[i][0] * inv, acc[i][1] * inv,
                                acc[i][2] * inv, acc[i][3] * inv);
        *(float4*)&g_o[((size_t)(b * NTOK + n)) * DMODEL + hq * HDIM + tx * 4] = o4;
    }
}

// =============================================================================
// Kernel 3: out = O @ Wo + bo
// =============================================================================
__global__ __launch_bounds__(256) void out_kernel(
    const float* __restrict__ Wo, const float* __restrict__ bo,
    float* __restrict__ out)
{
    __shared__ float As[16][68];
    __shared__ float Bs[16][68];

    const int tid = threadIdx.x;
    const int tx = tid & 15, ty = tid >> 4;
    const int m0   = blockIdx.y * 64;
    const int colb = blockIdx.x * 64;

    float c[4][4] = {};
    const int arow = tid >> 2, ac = tid & 3;
    const int brow = tid >> 4, bc = (tid & 15) * 4;

    for (int k0 = 0; k0 < 1024; k0 += 16) {
        float4 av = *(const float4*)&g_o[(size_t)(m0 + arow) * 1024 + k0 + ac * 4];
        As[ac*4+0][arow] = av.x; As[ac*4+1][arow] = av.y;
        As[ac*4+2][arow] = av.z; As[ac*4+3][arow] = av.w;
        *(float4*)&Bs[brow][bc] = *(const float4*)&Wo[(size_t)(k0 + brow) * 1024 + colb + bc];
        __syncthreads();
        #pragma unroll
        for (int kk = 0; kk < 16; kk++) {
            float4 a = *(const float4*)&As[kk][ty * 4];
            float4 b = *(const float4*)&Bs[kk][tx * 4];
            float aa[4] = {a.x, a.y, a.z, a.w};
            float bb[4] = {b.x, b.y, b.z, b.w};
            #pragma unroll
            for (int i = 0; i < 4; i++)
                #pragma unroll
                for (int j = 0; j < 4; j++)
                    c[i][j] += aa[i] * bb[j];
        }
        __syncthreads();
    }

    #pragma unroll
    for (int i = 0; i < 4; i++) {
        int m = m0 + ty * 4 + i;
        float4 o4;
        o4.x = c[i][0] + bo[colb + tx * 4 + 0];
        o4.y = c[i][1] + bo[colb + tx * 4 + 1];
        o4.z = c[i][2] + bo[colb + tx * 4 + 2];
        o4.w = c[i][3] + bo[colb + tx * 4 + 3];
        *(float4*)&out[(size_t)m * 1024 + colb + tx * 4] = o4;
    }
}

// =============================================================================
extern "C" void kernel_launch(void* const* d_in, const int* in_sizes, int n_in,
                              void* d_out, int out_size)
{
    const float* x  = (const float*)d_in[0];
    const float* Wq = (const float*)d_in[1];
    const float* bq = (const float*)d_in[2];
    const float* Wk = (const float*)d_in[3];
    const float* bk = (const float*)d_in[4];
    const float* Wv = (const float*)d_in[5];
    const float* bv = (const float*)d_in[6];
    const float* Wo = (const float*)d_in[7];
    const float* bo = (const float*)d_in[8];
    const float* qn = (const float*)d_in[9];
    const float* kn = (const float*)d_in[10];
    float* out = (float*)d_out;

    qkv_kernel<<<dim3(24, 64), 256>>>(x, Wq, bq, Wk, bk, Wv, bv, qn, kn);
    attn_kernel<<<dim3(32, 32), 256>>>();
    out_kernel<<<dim3(16, 64), 256>>>(Wo, bo, out);
}

// round 2
// speedup vs baseline: 2.2962x; 2.2962x over previous
#include <cuda_runtime.h>
#include <math.h>
#include <stdint.h>

// Problem constants (fixed)
#define NTOK 2048

// ---------------- scratch (device globals) ----------------
__device__ float g_q[(size_t)2 * 16 * NTOK * 64]; // [b][h][n][d]  (tf32-rounded, q pre-scaled)
__device__ float g_k[(size_t)2 * 4  * NTOK * 64]; // [b][kv][n][d] (tf32-rounded)
__device__ float g_v[(size_t)2 * 4  * NTOK * 64]; // [b][kv][n][d] (tf32-rounded)
__device__ float g_o[(size_t)4096 * 1024];        // [m][1024]     (tf32-rounded)

__device__ __forceinline__ float F2TF(float x) {
    uint32_t r; asm("cvt.rna.tf32.f32 %0, %1;" : "=r"(r) : "f"(x));
    return __uint_as_float(r);
}

// D += A(16x8, tf32, row) * B(8x8, tf32, col)
__device__ __forceinline__ void mma8(float* d, uint32_t a0, uint32_t a1, uint32_t a2,
                                     uint32_t a3, uint32_t b0, uint32_t b1) {
    asm volatile(
        "mma.sync.aligned.m16n8k8.row.col.f32.tf32.tf32.f32 "
        "{%0,%1,%2,%3},{%4,%5,%6,%7},{%8,%9},{%0,%1,%2,%3};\n"
        : "+f"(d[0]), "+f"(d[1]), "+f"(d[2]), "+f"(d[3])
        : "r"(a0), "r"(a1), "r"(a2), "r"(a3), "r"(b0), "r"(b1));
}

// =============================================================================
// Kernel 1: QKV GEMM (tf32 mma) + bias + RMSNorm + 3D RoPE + q-scale
//   block: 128 rows x 64 cols (one head). 8 warps, each 16x64.
// =============================================================================
__global__ __launch_bounds__(256) void qkv_kernel(
    const float* __restrict__ x,
    const float* __restrict__ Wq, const float* __restrict__ bq,
    const float* __restrict__ Wk, const float* __restrict__ bk,
    const float* __restrict__ Wv, const float* __restrict__ bv,
    const float* __restrict__ qn, const float* __restrict__ kn)
{
    __shared__ float As[128 * 36];  // [m][k] pad->36
    __shared__ float Bs[32 * 68];   // [k][n] pad->68

    const int tid = threadIdx.x;
    const int w = tid >> 5, lane = tid & 31, g = lane >> 2, c = lane & 3;
    const int m0 = blockIdx.y * 128;
    const int colb = blockIdx.x * 64;

    const float* Bmat; const float* bias; int ldb, seg, colloc;
    if (colb < 1024)      { Bmat = Wq; bias = bq; ldb = 1024; seg = 0; colloc = colb; }
    else if (colb < 1280) { Bmat = Wk; bias = bk; ldb = 256;  seg = 1; colloc = colb - 1024; }
    else                  { Bmat = Wv; bias = bv; ldb = 256;  seg = 2; colloc = colb - 1280; }

    float acc[8][4] = {};
    const int ar = tid >> 3, ac4 = (tid & 7) * 4;
    const int br = tid >> 4, bc4 = (tid & 15) * 4;

    for (int k0 = 0; k0 < 1024; k0 += 32) {
        #pragma unroll
        for (int p = 0; p < 4; p++) {
            float4 v = *(const float4*)&x[(size_t)(m0 + p * 32 + ar) * 1024 + k0 + ac4];
            float* dst = &As[(p * 32 + ar) * 36 + ac4];
            dst[0] = F2TF(v.x); dst[1] = F2TF(v.y); dst[2] = F2TF(v.z); dst[3] = F2TF(v.w);
        }
        #pragma unroll
        for (int p = 0; p < 2; p++) {
            float4 v = *(const float4*)&Bmat[(size_t)(k0 + p * 16 + br) * ldb + colloc + bc4];
            float* dst = &Bs[(p * 16 + br) * 68 + bc4];
            dst[0] = F2TF(v.x); dst[1] = F2TF(v.y); dst[2] = F2TF(v.z); dst[3] = F2TF(v.w);
        }
        __syncthreads();
        #pragma unroll
        for (int ks = 0; ks < 4; ks++) {
            const float* ap = &As[(w * 16 + g) * 36 + ks * 8 + c];
            uint32_t a0 = __float_as_uint(ap[0]);
            uint32_t a1 = __float_as_uint(ap[8 * 36]);
            uint32_t a2 = __float_as_uint(ap[4]);
            uint32_t a3 = __float_as_uint(ap[8 * 36 + 4]);
            #pragma unroll
            for (int nt = 0; nt < 8; nt++) {
                uint32_t b0 = __float_as_uint(Bs[(ks * 8 + c) * 68 + nt * 8 + g]);
                uint32_t b1 = __float_as_uint(Bs[(ks * 8 + c + 4) * 68 + nt * 8 + g]);
                mma8(acc[nt], a0, a1, a2, a3, b0, b1);
            }
        }
        __syncthreads();
    }

    // bias
    #pragma unroll
    for (int nt = 0; nt < 8; nt++) {
        float b0v = bias[colloc + nt * 8 + 2 * c];
        float b1v = bias[colloc + nt * 8 + 2 * c + 1];
        acc[nt][0] += b0v; acc[nt][1] += b1v; acc[nt][2] += b0v; acc[nt][3] += b1v;
    }

    const int m_a = m0 + w * 16 + g;
    const int b_ = m_a >> 11;
    const int n0 = m_a & 2047, n1 = n0 + 8;
    const int head = colloc >> 6;

    if (seg == 2) {
        float* vb = &g_v[((size_t)(b_ * 4 + head)) * NTOK * 64];
        #pragma unroll
        for (int nt = 0; nt < 8; nt++) {
            int d0 = nt * 8 + 2 * c;
            *(float2*)&vb[(size_t)n0 * 64 + d0] = make_float2(F2TF(acc[nt][0]), F2TF(acc[nt][1]));
            *(float2*)&vb[(size_t)n1 * 64 + d0] = make_float2(F2TF(acc[nt][2]), F2TF(acc[nt][3]));
        }
        return;
    }

    // RMSNorm over the 64-wide head dim (fully intra-warp: 16 vals/thread/row + 2 shfls)
    const float* nw = (seg == 0) ? qn : kn;
    float ss0 = 0.f, ss1 = 0.f;
    #pragma unroll
    for (int nt = 0; nt < 8; nt++) {
        ss0 += acc[nt][0] * acc[nt][0] + acc[nt][1] * acc[nt][1];
        ss1 += acc[nt][2] * acc[nt][2] + acc[nt][3] * acc[nt][3];
    }
    ss0 += __shfl_xor_sync(~0u, ss0, 1); ss0 += __shfl_xor_sync(~0u, ss0, 2);
    ss1 += __shfl_xor_sync(~0u, ss1, 1); ss1 += __shfl_xor_sync(~0u, ss1, 2);
    float rs0 = rsqrtf(ss0 * (1.f / 64.f) + 1e-6f);
    float rs1 = rsqrtf(ss1 * (1.f / 64.f) + 1e-6f);
    #pragma unroll
    for (int nt = 0; nt < 8; nt++) {
        float w0 = nw[nt * 8 + 2 * c], w1 = nw[nt * 8 + 2 * c + 1];
        acc[nt][0] *= rs0 * w0; acc[nt][1] *= rs0 * w1;
        acc[nt][2] *= rs1 * w0; acc[nt][3] *= rs1 * w1;
    }

    // factored 3D RoPE: dt=16 (nt0/1), dh=16 (nt2/3), dw=32 (nt4..7)
    // pairing offsets 8/8/16 are multiples of the 8-wide n-tile: partner is same
    // register slot of nt^1 (t,h) or nt^2 (w) — fully in-register.
    float pos0[3] = {(float)(n0 >> 8), (float)((n0 >> 4) & 15), (float)(n0 & 15)};
    float pos1[3] = {(float)(n1 >> 8), (float)((n1 >> 4) & 15), (float)(n1 & 15)};
    float out[8][4];
    #pragma unroll
    for (int nt = 0; nt < 8; nt++) {
        int pnt = (nt < 4) ? (nt ^ 1) : (nt ^ 2);
        float sg = ((nt < 4) ? ((nt & 1) == 0) : ((nt & 2) == 0)) ? -1.f : 1.f;
        int ax = (nt < 2) ? 0 : (nt < 4 ? 1 : 2);
        float halfinv = (nt < 4) ? (1.f / 8.f) : (1.f / 16.f);
        #pragma unroll
        for (int e = 0; e < 2; e++) {
            float f = (nt < 4) ? (float)(2 * c + e) : (float)((nt & 1) * 8 + 2 * c + e);
            float inv = __powf(10000.f, -f * halfinv);
            float s0, c0, s1, c1;
            __sincosf(pos0[ax] * inv, &s0, &c0);
            __sincosf(pos1[ax] * inv, &s1, &c1);
            out[nt][e]     = acc[nt][e]     * c0 + sg * acc[pnt][e]     * s0;
            out[nt][2 + e] = acc[nt][2 + e] * c1 + sg * acc[pnt][2 + e] * s1;
        }
    }
    float scale = (seg == 0) ? 0.125f : 1.f;   // fold HD^-0.5 into q
    float* qb = (seg == 0) ? &g_q[((size_t)(b_ * 16 + head)) * NTOK * 64]
                           : &g_k[((size_t)(b_ * 4 + head)) * NTOK * 64];
    #pragma unroll
    for (int nt = 0; nt < 8; nt++) {
        int d0 = nt * 8 + 2 * c;
        *(float2*)&qb[(size_t)n0 * 64 + d0] =
            make_float2(F2TF(out[nt][0] * scale), F2TF(out[nt][1] * scale));
        *(float2*)&qb[(size_t)n1 * 64 + d0] =
            make_float2(F2TF(out[nt][2] * scale), F2TF(out[nt][3] * scale));
    }
}

// =============================================================================
// Kernel 2: flash attention, tf32 mma. 128 q-rows/block, 8 warps (16 q each),
//   64-key tiles, online softmax, P re-fragmented via warp-private smem.
// =============================================================================
__global__ __launch_bounds__(256, 2) void attn_kernel()
{
    extern __shared__ float sm[];
    float* Qs = sm;                       // 128 x 68   [q][d]
    float* Ks = sm + 128 * 68;            // 64 x 68    [key][d]
    float* Vs = Ks + 64 * 68;             // 64 x 68    [key][d]
    float* Pbase = Vs + 64 * 68;          // 8 x (16 x 68)

    const int tid = threadIdx.x;
    const int w = tid >> 5, lane = tid & 31, g = lane >> 2, c = lane & 3;
    float* Pw = Pbase + w * 16 * 68;
    const int q0 = blockIdx.x * 128;
    const int bh = blockIdx.y;
    const int b_ = bh >> 4, h = bh & 15, kv = h >> 2;

    const float* qg = &g_q[((size_t)(b_ * 16 + h)) * NTOK * 64];
    const float* kg = &g_k[((size_t)(b_ * 4 + kv)) * NTOK * 64];
    const float* vg = &g_v[((size_t)(b_ * 4 + kv)) * NTOK * 64];

    {
        int r = tid >> 1, e = tid & 1;
        #pragma unroll
        for (int i = 0; i < 8; i++) {
            int col = e * 32 + i * 4;
            *(float4*)&Qs[r * 68 + col] = *(const float4*)&qg[(size_t)(q0 + r) * 64 + col];
        }
    }

    float o[8][4] = {};
    float mrow[2] = {-1e30f, -1e30f};
    float lsum[2] = {0.f, 0.f};

    for (int kt = 0; kt < NTOK; kt += 64) {
        __syncthreads();
        {
            int r = tid >> 2, c4 = tid & 3;
            #pragma unroll
            for (int i = 0; i < 4; i++) {
                int col = c4 * 16 + i * 4;
                *(float4*)&Ks[r * 68 + col] = *(const float4*)&kg[(size_t)(kt + r) * 64 + col];
                *(float4*)&Vs[r * 68 + col] = *(const float4*)&vg[(size_t)(kt + r) * 64 + col];
            }
        }
        __syncthreads();

        // S = Q K^T  (16x64 per warp; q already carries the 1/8 scale)
        float s[8][4] = {};
        #pragma unroll
        for (int ks = 0; ks < 8; ks++) {
            const float* ap = &Qs[(w * 16 + g) * 68 + ks * 8 + c];
            uint32_t a0 = __float_as_uint(ap[0]);
            uint32_t a1 = __float_as_uint(ap[8 * 68]);
            uint32_t a2 = __float_as_uint(ap[4]);
            uint32_t a3 = __float_as_uint(ap[8 * 68 + 4]);
            #pragma unroll
            for (int nt = 0; nt < 8; nt++) {
                uint32_t b0 = __float_as_uint(Ks[(nt * 8 + g) * 68 + ks * 8 + c]);
                uint32_t b1 = __float_as_uint(Ks[(nt * 8 + g) * 68 + ks * 8 + c + 4]);
                mma8(s[nt], a0, a1, a2, a3, b0, b1);
            }
        }

        // online softmax (rows r=g and g+8 of this warp's band)
        #pragma unroll
        for (int rsel = 0; rsel < 2; rsel++) {
            float mx = -1e30f;
            #pragma unroll
            for (int nt = 0; nt < 8; nt++)
                mx = fmaxf(mx, fmaxf(s[nt][2 * rsel], s[nt][2 * rsel + 1]));
            mx = fmaxf(mx, __shfl_xor_sync(~0u, mx, 1));
            mx = fmaxf(mx, __shfl_xor_sync(~0u, mx, 2));
            float mn = fmaxf(mrow[rsel], mx);
            float corr = __expf(mrow[rsel] - mn);
            mrow[rsel] = mn;
            float rs = 0.f;
            #pragma unroll
            for (int nt = 0; nt < 8; nt++) {
                float p0 = __expf(s[nt][2 * rsel] - mn);
                float p1 = __expf(s[nt][2 * rsel + 1] - mn);
                s[nt][2 * rsel] = p0; s[nt][2 * rsel + 1] = p1;
                rs += p0 + p1;
            }
            rs += __shfl_xor_sync(~0u, rs, 1);
            rs += __shfl_xor_sync(~0u, rs, 2);
            lsum[rsel] = lsum[rsel] * corr + rs;
            #pragma unroll
            for (int nt = 0; nt < 8; nt++) { o[nt][2 * rsel] *= corr; o[nt][2 * rsel + 1] *= corr; }
        }

        // stage P (C-frag -> row-major smem, warp-private)
        #pragma unroll
        for (int nt = 0; nt < 8; nt++) {
            *(float2*)&Pw[g * 68 + nt * 8 + 2 * c] =
                make_float2(F2TF(s[nt][0]), F2TF(s[nt][1]));
            *(float2*)&Pw[(g + 8) * 68 + nt * 8 + 2 * c] =
                make_float2(F2TF(s[nt][2]), F2TF(s[nt][3]));
        }
        __syncwarp();

        // O += P V
        #pragma unroll
        for (int ks = 0; ks < 8; ks++) {
            const float* pp = &Pw[g * 68 + ks * 8 + c];
            uint32_t a0 = __float_as_uint(pp[0]);
            uint32_t a1 = __float_as_uint(pp[8 * 68]);
            uint32_t a2 = __float_as_uint(pp[4]);
            uint32_t a3 = __float_as_uint(pp[8 * 68 + 4]);
            #pragma unroll
            for (int nt = 0; nt < 8; nt++) {
                uint32_t b0 = __float_as_uint(Vs[(ks * 8 + c) * 68 + nt * 8 + g]);
                uint32_t b1 = __float_as_uint(Vs[(ks * 8 + c + 4) * 68 + nt * 8 + g]);
                mma8(o[nt], a0, a1, a2, a3, b0, b1);
            }
        }
    }

    float inv0 = 1.f / lsum[0], inv1 = 1.f / lsum[1];
    int n0 = q0 + w * 16 + g, n1 = n0 + 8;
    float* ob0 = &g_o[((size_t)(b_ * NTOK + n0)) * 1024 + h * 64];
    float* ob1 = &g_o[((size_t)(b_ * NTOK + n1)) * 1024 + h * 64];
    #pragma unroll
    for (int nt = 0; nt < 8; nt++) {
        int d0 = nt * 8 + 2 * c;
        *(float2*)&ob0[d0] = make_float2(F2TF(o[nt][0] * inv0), F2TF(o[nt][1] * inv0));
        *(float2*)&ob1[d0] = make_float2(F2TF(o[nt][2] * inv1), F2TF(o[nt][3] * inv1));
    }
}

// =============================================================================
// Kernel 3: out = O @ Wo + bo  (tf32 mma; O pre-rounded to tf32)
// =============================================================================
__global__ __launch_bounds__(256) void out_kernel(
    const float* __restrict__ Wo, const float* __restrict__ bo,
    float* __restrict__ out)
{
    __shared__ float As[128 * 36];
    __shared__ float Bs[32 * 68];

    const int tid = threadIdx.x;
    const int w = tid >> 5, lane = tid & 31, g = lane >> 2, c = lane & 3;
    const int m0 = blockIdx.y * 128;
    const int colb = blockIdx.x * 64;

    float acc[8][4] = {};
    const int ar = tid >> 3, ac4 = (tid & 7) * 4;
    const int br = tid >> 4, bc4 = (tid & 15) * 4;

    for (int k0 = 0; k0 < 1024; k0 += 32) {
        #pragma unroll
        for (int p = 0; p < 4; p++) {
            *(float4*)&As[(p * 32 + ar) * 36 + ac4] =
                *(const float4*)&g_o[(size_t)(m0 + p * 32 + ar) * 1024 + k0 + ac4];
        }
        #pragma unroll
        for (int p = 0; p < 2; p++) {
            float4 v = *(const float4*)&Wo[(size_t)(k0 + p * 16 + br) * 1024 + colb + bc4];
            float* dst = &Bs[(p * 16 + br) * 68 + bc4];
            dst[0] = F2TF(v.x); dst[1] = F2TF(v.y); dst[2] = F2TF(v.z); dst[3] = F2TF(v.w);
        }
        __syncthreads();
        #pragma unroll
        for (int ks = 0; ks < 4; ks++) {
            const float* ap = &As[(w * 16 + g) * 36 + ks * 8 + c];
            uint32_t a0 = __float_as_uint(ap[0]);
            uint32_t a1 = __float_as_uint(ap[8 * 36]);
            uint32_t a2 = __float_as_uint(ap[4]);
            uint32_t a3 = __float_as_uint(ap[8 * 36 + 4]);
            #pragma unroll
            for (int nt = 0; nt < 8; nt++) {
                uint32_t b0 = __float_as_uint(Bs[(ks * 8 + c) * 68 + nt * 8 + g]);
                uint32_t b1 = __float_as_uint(Bs[(ks * 8 + c + 4) * 68 + nt * 8 + g]);
                mma8(acc[nt], a0, a1, a2, a3, b0, b1);
            }
        }
        __syncthreads();
    }

    int m_a = m0 + w * 16 + g;
    float* r0 = &out[(size_t)m_a * 1024 + colb];
    float* r1 = &out[(size_t)(m_a + 8) * 1024 + colb];
    #pragma unroll
    for (int nt = 0; nt < 8; nt++) {
        int d0 = nt * 8 + 2 * c;
        float b0v = bo[colb + d0], b1v = bo[colb + d0 + 1];
        *(float2*)&r0[d0] = make_float2(acc[nt][0] + b0v, acc[nt][1] + b1v);
        *(float2*)&r1[d0] = make_float2(acc[nt][2] + b0v, acc[nt][3] + b1v);
    }
}

// =============================================================================
extern "C" void kernel_launch(void* const* d_in, const int* in_sizes, int n_in,
                              void* d_out, int out_size)
{
    const float* x  = (const float*)d_in[0];
    const float* Wq = (const float*)d_in[1];
    const float* bq = (const float*)d_in[2];
    const float* Wk = (const float*)d_in[3];
    const float* bk = (const float*)d_in[4];
    const float* Wv = (const float*)d_in[5];
    const float* bv = (const float*)d_in[6];
    const float* Wo = (const float*)d_in[7];
    const float* bo = (const float*)d_in[8];
    const float* qn = (const float*)d_in[9];
    const float* kn = (const float*)d_in[10];
    float* out = (float*)d_out;

    static int smem_set = 0;
    const int attn_smem = (128 * 68 + 64 * 68 + 64 * 68 + 8 * 16 * 68) * 4; // 104448 B
    if (!smem_set) {
        cudaFuncSetAttribute(attn_kernel, cudaFuncAttributeMaxDynamicSharedMemorySize, attn_smem);
        smem_set = 1;
    }

    qkv_kernel<<<dim3(24, 32), 256>>>(x, Wq, bq, Wk, bk, Wv, bv, qn, kn);
    attn_kernel<<<dim3(16, 32), 256, attn_smem>>>();
    out_kernel<<<dim3(16, 32), 256>>>(Wo, bo, out);
}

// round 3
// speedup vs baseline: 2.4510x; 1.0674x over previous
#include <cuda_runtime.h>
#include <math.h>
#include <stdint.h>

#define NTOK 2048

// ---------------- scratch ----------------
__device__ float g_q [(size_t)2 * 16 * NTOK * 64]; // [b][h][n][d]   (tf32, q pre-scaled)
__device__ float g_k [(size_t)2 * 4  * NTOK * 64]; // [b][kv][n][d]  (tf32)
__device__ float g_vt[(size_t)2 * 4  * 64 * NTOK]; // [b][kv][d][n]  (tf32, TRANSPOSED)
__device__ float g_o [(size_t)4096 * 1024];        // [m][1024]      (tf32)

__device__ __forceinline__ float F2TF(float x) {
    uint32_t r; asm("cvt.rna.tf32.f32 %0, %1;" : "=r"(r) : "f"(x));
    return __uint_as_float(r);
}

// D += A(16x8 tf32 row) * B(8x8 tf32 col); slot mapping: slot c <-> stored 2c,
// slot c+4 <-> stored 2c+1 (consistent across A and B => arbitrary-but-valid).
__device__ __forceinline__ void mma8(float* d, float a0, float a1, float a2,
                                     float a3, float b0, float b1) {
    asm volatile(
        "mma.sync.aligned.m16n8k8.row.col.f32.tf32.tf32.f32 "
        "{%0,%1,%2,%3},{%4,%5,%6,%7},{%8,%9},{%0,%1,%2,%3};\n"
        : "+f"(d[0]), "+f"(d[1]), "+f"(d[2]), "+f"(d[3])
        : "r"(__float_as_uint(a0)), "r"(__float_as_uint(a1)),
          "r"(__float_as_uint(a2)), "r"(__float_as_uint(a3)),
          "r"(__float_as_uint(b0)), "r"(__float_as_uint(b1)));
}

// =============================================================================
// Kernel 1: QKV GEMM + bias + RMSNorm + 3D RoPE + q-scale.
//   128 threads, 4 warps; warp tile 32x64; block tile 128x64 (one head col-tile).
// =============================================================================
__global__ __launch_bounds__(128) void qkv_kernel(
    const float* __restrict__ x,
    const float* __restrict__ Wq, const float* __restrict__ bq,
    const float* __restrict__ Wk, const float* __restrict__ bk,
    const float* __restrict__ Wv, const float* __restrict__ bv,
    const float* __restrict__ qn, const float* __restrict__ kn)
{
    __shared__ float As[128 * 36];  // [m][k]  pad 36
    __shared__ float Bt[64 * 36];   // [n][k]  transposed, pad 36

    const int tid = threadIdx.x;
    const int w = tid >> 5, lane = tid & 31, g = lane >> 2, c = lane & 3;
    const int m0 = blockIdx.y * 128;
    const int colb = blockIdx.x * 64;

    const float* Bmat; const float* bias; int ldb, seg, colloc;
    if (colb < 1024)      { Bmat = Wq; bias = bq; ldb = 1024; seg = 0; colloc = colb; }
    else if (colb < 1280) { Bmat = Wk; bias = bk; ldb = 256;  seg = 1; colloc = colb - 1024; }
    else                  { Bmat = Wv; bias = bv; ldb = 256;  seg = 2; colloc = colb - 1280; }

    float acc[2][8][4] = {};
    const int ar = tid >> 3, ac4 = (tid & 7) * 4;   // A loader
    const int kr = tid >> 4, n4 = (tid & 15) * 4;   // B loader

    for (int k0 = 0; k0 < 1024; k0 += 32) {
        #pragma unroll
        for (int p = 0; p < 8; p++) {
            float4 v = *(const float4*)&x[(size_t)(m0 + p * 16 + ar) * 1024 + k0 + ac4];
            float* dst = &As[(p * 16 + ar) * 36 + ac4];
            dst[0] = F2TF(v.x); dst[1] = F2TF(v.y); dst[2] = F2TF(v.z); dst[3] = F2TF(v.w);
        }
        #pragma unroll
        for (int p = 0; p < 4; p++) {
            int k = p * 8 + kr;
            float4 v = *(const float4*)&Bmat[(size_t)(k0 + k) * ldb + colloc + n4];
            Bt[(n4 + 0) * 36 + k] = F2TF(v.x);
            Bt[(n4 + 1) * 36 + k] = F2TF(v.y);
            Bt[(n4 + 2) * 36 + k] = F2TF(v.z);
            Bt[(n4 + 3) * 36 + k] = F2TF(v.w);
        }
        __syncthreads();
        #pragma unroll
        for (int ks = 0; ks < 4; ks++) {
            float2 fa[4];
            #pragma unroll
            for (int r = 0; r < 4; r++)
                fa[r] = *(const float2*)&As[(w * 32 + r * 8 + g) * 36 + ks * 8 + 2 * c];
            #pragma unroll
            for (int nt = 0; nt < 8; nt++) {
                float2 wb = *(const float2*)&Bt[(nt * 8 + g) * 36 + ks * 8 + 2 * c];
                mma8(acc[0][nt], fa[0].x, fa[1].x, fa[0].y, fa[1].y, wb.x, wb.y);
                mma8(acc[1][nt], fa[2].x, fa[3].x, fa[2].y, fa[3].y, wb.x, wb.y);
            }
        }
        __syncthreads();
    }

    // bias
    #pragma unroll
    for (int nt = 0; nt < 8; nt++) {
        float b0v = bias[colloc + nt * 8 + 2 * c];
        float b1v = bias[colloc + nt * 8 + 2 * c + 1];
        #pragma unroll
        for (int mt = 0; mt < 2; mt++) {
            acc[mt][nt][0] += b0v; acc[mt][nt][1] += b1v;
            acc[mt][nt][2] += b0v; acc[mt][nt][3] += b1v;
        }
    }

    const int head = colloc >> 6;

    if (seg == 2) {
        // V -> transposed [b][kv][d][n]
        #pragma unroll
        for (int mt = 0; mt < 2; mt++) {
            int m_a = m0 + w * 32 + mt * 16 + g;
            int b_ = m_a >> 11, n0 = m_a & 2047, n1 = n0 + 8;
            float* vb = &g_vt[((size_t)(b_ * 4 + head)) * 64 * NTOK];
            #pragma unroll
            for (int nt = 0; nt < 8; nt++) {
                int d0 = nt * 8 + 2 * c;
                vb[(size_t)d0 * NTOK + n0]       = F2TF(acc[mt][nt][0]);
                vb[(size_t)(d0 + 1) * NTOK + n0] = F2TF(acc[mt][nt][1]);
                vb[(size_t)d0 * NTOK + n1]       = F2TF(acc[mt][nt][2]);
                vb[(size_t)(d0 + 1) * NTOK + n1] = F2TF(acc[mt][nt][3]);
            }
        }
        return;
    }

    // RMSNorm over 64-wide head dim (intra-warp)
    const float* nw = (seg == 0) ? qn : kn;
    #pragma unroll
    for (int mt = 0; mt < 2; mt++) {
        float ss0 = 0.f, ss1 = 0.f;
        #pragma unroll
        for (int nt = 0; nt < 8; nt++) {
            ss0 += acc[mt][nt][0] * acc[mt][nt][0] + acc[mt][nt][1] * acc[mt][nt][1];
            ss1 += acc[mt][nt][2] * acc[mt][nt][2] + acc[mt][nt][3] * acc[mt][nt][3];
        }
        ss0 += __shfl_xor_sync(~0u, ss0, 1); ss0 += __shfl_xor_sync(~0u, ss0, 2);
        ss1 += __shfl_xor_sync(~0u, ss1, 1); ss1 += __shfl_xor_sync(~0u, ss1, 2);
        float rs0 = rsqrtf(ss0 * (1.f / 64.f) + 1e-6f);
        float rs1 = rsqrtf(ss1 * (1.f / 64.f) + 1e-6f);
        #pragma unroll
        for (int nt = 0; nt < 8; nt++) {
            float w0 = nw[nt * 8 + 2 * c], w1 = nw[nt * 8 + 2 * c + 1];
            acc[mt][nt][0] *= rs0 * w0; acc[mt][nt][1] *= rs0 * w1;
            acc[mt][nt][2] *= rs1 * w0; acc[mt][nt][3] *= rs1 * w1;
        }
    }

    // factored 3D RoPE, in-place on (lo,hi) tile pairs:
    //   t: tiles (0,1), h: (2,3), w: (4,6) and (5,7)
    const int lo_[4] = {0, 2, 4, 5};
    const int hi_[4] = {1, 3, 6, 7};
    #pragma unroll
    for (int mt = 0; mt < 2; mt++) {
        int m_a = m0 + w * 32 + mt * 16 + g;
        int n0 = m_a & 2047, n1 = n0 + 8;
        float posr[2][3] = {
            {(float)(n0 >> 8), (float)((n0 >> 4) & 15), (float)(n0 & 15)},
            {(float)(n1 >> 8), (float)((n1 >> 4) & 15), (float)(n1 & 15)}};
        #pragma unroll
        for (int pi = 0; pi < 4; pi++) {
            int lo = lo_[pi], hi = hi_[pi];
            int ax = (pi == 0) ? 0 : (pi == 1 ? 1 : 2);
            float halfinv = (pi < 2) ? (1.f / 8.f) : (1.f / 16.f);
            #pragma unroll
            for (int e = 0; e < 2; e++) {
                float f = (pi < 2) ? (float)(2 * c + e)
                                   : (float)((lo & 1) * 8 + 2 * c + e);
                float inv = __powf(10000.f, -f * halfinv);
                #pragma unroll
                for (int r = 0; r < 2; r++) {
                    float sv, cv;
                    __sincosf(posr[r][ax] * inv, &sv, &cv);
                    float xl = acc[mt][lo][2 * r + e];
                    float xh = acc[mt][hi][2 * r + e];
                    acc[mt][lo][2 * r + e] = xl * cv - xh * sv;
                    acc[mt][hi][2 * r + e] = xh * cv + xl * sv;
                }
            }
        }
    }

    float scale = (seg == 0) ? 0.125f : 1.f;
    #pragma unroll
    for (int mt = 0; mt < 2; mt++) {
        int m_a = m0 + w * 32 + mt * 16 + g;
        int b_ = m_a >> 11, n0 = m_a & 2047, n1 = n0 + 8;
        float* qb = (seg == 0) ? &g_q[((size_t)(b_ * 16 + head)) * NTOK * 64]
                               : &g_k[((size_t)(b_ * 4 + head)) * NTOK * 64];
        #pragma unroll
        for (int nt = 0; nt < 8; nt++) {
            int d0 = nt * 8 + 2 * c;
            *(float2*)&qb[(size_t)n0 * 64 + d0] =
                make_float2(F2TF(acc[mt][nt][0] * scale), F2TF(acc[mt][nt][1] * scale));
            *(float2*)&qb[(size_t)n1 * 64 + d0] =
                make_float2(F2TF(acc[mt][nt][2] * scale), F2TF(acc[mt][nt][3] * scale));
        }
    }
}

// =============================================================================
// Kernel 2: flash attention. 256 threads, 8 warps x 16 q-rows; 64-key tiles.
//   Q fragments register-resident; P stays in registers (C-frag == A-frag under
//   slot remap; key-perm composes to identity with V stored [d][n]).
// =============================================================================
__global__ __launch_bounds__(256, 2) void attn_kernel()
{
    __shared__ float Ks[64 * 68];   // [key][d]
    __shared__ float Vs[64 * 68];   // [d][key]

    const int tid = threadIdx.x;
    const int w = tid >> 5, lane = tid & 31, g = lane >> 2, c = lane & 3;
    const int q0 = blockIdx.x * 128;
    const int bh = blockIdx.y;
    const int b_ = bh >> 4, h = bh & 15, kv = h >> 2;

    const float* qg = &g_q[((size_t)(b_ * 16 + h)) * NTOK * 64];
    const float* kg = &g_k[((size_t)(b_ * 4 + kv)) * NTOK * 64];
    const float* vg = &g_vt[((size_t)(b_ * 4 + kv)) * 64 * NTOK];

    // Q fragments: rows (q0+w*16+g, +8), cols ks*8+2c/+1 -> register resident
    float qf[8][4];
    {
        const float* r0 = &qg[(size_t)(q0 + w * 16 + g) * 64];
        const float* r1 = r0 + 8 * 64;
        #pragma unroll
        for (int ks = 0; ks < 8; ks++) {
            float2 a = *(const float2*)&r0[ks * 8 + 2 * c];
            float2 b = *(const float2*)&r1[ks * 8 + 2 * c];
            qf[ks][0] = a.x; qf[ks][1] = b.x; qf[ks][2] = a.y; qf[ks][3] = b.y;
        }
    }

    float o[8][4] = {};
    float mrow[2] = {-1e30f, -1e30f};
    float lsum[2] = {0.f, 0.f};

    const int lr = tid >> 2, lc = (tid & 3) * 16;

    for (int kt = 0; kt < NTOK; kt += 64) {
        __syncthreads();
        #pragma unroll
        for (int i = 0; i < 4; i++) {
            *(float4*)&Ks[lr * 68 + lc + i * 4] =
                *(const float4*)&kg[(size_t)(kt + lr) * 64 + lc + i * 4];
            *(float4*)&Vs[lr * 68 + lc + i * 4] =
                *(const float4*)&vg[(size_t)lr * NTOK + kt + lc + i * 4];
        }
        __syncthreads();

        // S = Q K^T
        float s[8][4] = {};
        #pragma unroll
        for (int ks = 0; ks < 8; ks++) {
            #pragma unroll
            for (int nt = 0; nt < 8; nt++) {
                float2 kb = *(const float2*)&Ks[(nt * 8 + g) * 68 + ks * 8 + 2 * c];
                mma8(s[nt], qf[ks][0], qf[ks][1], qf[ks][2], qf[ks][3], kb.x, kb.y);
            }
        }

        // online softmax (rows g, g+8)
        #pragma unroll
        for (int rsel = 0; rsel < 2; rsel++) {
            float mx = -1e30f;
            #pragma unroll
            for (int nt = 0; nt < 8; nt++)
                mx = fmaxf(mx, fmaxf(s[nt][2 * rsel], s[nt][2 * rsel + 1]));
            mx = fmaxf(mx, __shfl_xor_sync(~0u, mx, 1));
            mx = fmaxf(mx, __shfl_xor_sync(~0u, mx, 2));
            float mn = fmaxf(mrow[rsel], mx);
            float corr = __expf(mrow[rsel] - mn);
            mrow[rsel] = mn;
            float rs = 0.f;
            #pragma unroll
            for (int nt = 0; nt < 8; nt++) {
                float p0 = __expf(s[nt][2 * rsel] - mn);
                float p1 = __expf(s[nt][2 * rsel + 1] - mn);
                s[nt][2 * rsel] = p0; s[nt][2 * rsel + 1] = p1;
                rs += p0 + p1;
            }
            rs += __shfl_xor_sync(~0u, rs, 1);
            rs += __shfl_xor_sync(~0u, rs, 2);
            lsum[rsel] = lsum[rsel] * corr + rs;
            #pragma unroll
            for (int nt = 0; nt < 8; nt++) { o[nt][2 * rsel] *= corr; o[nt][2 * rsel + 1] *= corr; }
        }

        // O += P V : S accumulator reused directly as A fragment
        #pragma unroll
        for (int ks = 0; ks < 8; ks++) {
            float a0 = F2TF(s[ks][0]);
            float a1 = F2TF(s[ks][2]);
            float a2 = F2TF(s[ks][1]);
            float a3 = F2TF(s[ks][3]);
            #pragma unroll
            for (int nt = 0; nt < 8; nt++) {
                float2 vb = *(const float2*)&Vs[(nt * 8 + g) * 68 + ks * 8 + 2 * c];
                mma8(o[nt], a0, a1, a2, a3, vb.x, vb.y);
            }
        }
    }

    float inv0 = 1.f / lsum[0], inv1 = 1.f / lsum[1];
    int n0 = q0 + w * 16 + g, n1 = n0 + 8;
    float* ob0 = &g_o[((size_t)(b_ * NTOK + n0)) * 1024 + h * 64];
    float* ob1 = &g_o[((size_t)(b_ * NTOK + n1)) * 1024 + h * 64];
    #pragma unroll
    for (int nt = 0; nt < 8; nt++) {
        int d0 = nt * 8 + 2 * c;
        *(float2*)&ob0[d0] = make_float2(F2TF(o[nt][0] * inv0), F2TF(o[nt][1] * inv0));
        *(float2*)&ob1[d0] = make_float2(F2TF(o[nt][2] * inv1), F2TF(o[nt][3] * inv1));
    }
}

// =============================================================================
// Kernel 3: out = O @ Wo + bo. 128 threads, warp tile 32x64.
// =============================================================================
__global__ __launch_bounds__(128) void out_kernel(
    const float* __restrict__ Wo, const float* __restrict__ bo,
    float* __restrict__ out)
{
    __shared__ float As[128 * 36];
    __shared__ float Bt[64 * 36];

    const int tid = threadIdx.x;
    const int w = tid >> 5, lane = tid & 31, g = lane >> 2, c = lane & 3;
    const int m0 = blockIdx.y * 128;
    const int colb = blockIdx.x * 64;

    float acc[2][8][4] = {};
    const int ar = tid >> 3, ac4 = (tid & 7) * 4;
    const int kr = tid >> 4, n4 = (tid & 15) * 4;

    for (int k0 = 0; k0 < 1024; k0 += 32) {
        #pragma unroll
        for (int p = 0; p < 8; p++) {
            *(float4*)&As[(p * 16 + ar) * 36 + ac4] =
                *(const float4*)&g_o[(size_t)(m0 + p * 16 + ar) * 1024 + k0 + ac4];
        }
        #pragma unroll
        for (int p = 0; p < 4; p++) {
            int k = p * 8 + kr;
            float4 v = *(const float4*)&Wo[(size_t)(k0 + k) * 1024 + colb + n4];
            Bt[(n4 + 0) * 36 + k] = F2TF(v.x);
            Bt[(n4 + 1) * 36 + k] = F2TF(v.y);
            Bt[(n4 + 2) * 36 + k] = F2TF(v.z);
            Bt[(n4 + 3) * 36 + k] = F2TF(v.w);
        }
        __syncthreads();
        #pragma unroll
        for (int ks = 0; ks < 4; ks++) {
            float2 fa[4];
            #pragma unroll
            for (int r = 0; r < 4; r++)
                fa[r] = *(const float2*)&As[(w * 32 + r * 8 + g) * 36 + ks * 8 + 2 * c];
            #pragma unroll
            for (int nt = 0; nt < 8; nt++) {
                float2 wb = *(const float2*)&Bt[(nt * 8 + g) * 36 + ks * 8 + 2 * c];
                mma8(acc[0][nt], fa[0].x, fa[1].x, fa[0].y, fa[1].y, wb.x, wb.y);
                mma8(acc[1][nt], fa[2].x, fa[3].x, fa[2].y, fa[3].y, wb.x, wb.y);
            }
        }
        __syncthreads();
    }

    #pragma unroll
    for (int mt = 0; mt < 2; mt++) {
        int m_a = m0 + w * 32 + mt * 16 + g;
        float* r0 = &out[(size_t)m_a * 1024 + colb];
        float* r1 = &out[(size_t)(m_a + 8) * 1024 + colb];
        #pragma unroll
        for (int nt = 0; nt < 8; nt++) {
            int d0 = nt * 8 + 2 * c;
            float b0v = bo[colb + d0], b1v = bo[colb + d0 + 1];
            *(float2*)&r0[d0] = make_float2(acc[mt][nt][0] + b0v, acc[mt][nt][1] + b1v);
            *(float2*)&r1[d0] = make_float2(acc[mt][nt][2] + b0v, acc[mt][nt][3] + b1v);
        }
    }
}

// =============================================================================
extern "C" void kernel_launch(void* const* d_in, const int* in_sizes, int n_in,
                              void* d_out, int out_size)
{
    const float* x  = (const float*)d_in[0];
    const float* Wq = (const float*)d_in[1];
    const float* bq = (const float*)d_in[2];
    const float* Wk = (const float*)d_in[3];
    const float* bk = (const float*)d_in[4];
    const float* Wv = (const float*)d_in[5];
    const float* bv = (const float*)d_in[6];
    const float* Wo = (const float*)d_in[7];
    const float* bo = (const float*)d_in[8];
    const float* qn = (const float*)d_in[9];
    const float* kn = (const float*)d_in[10];
    float* out = (float*)d_out;

    qkv_kernel<<<dim3(24, 32), 128>>>(x, Wq, bq, Wk, bk, Wv, bv, qn, kn);
    attn_kernel<<<dim3(16, 32), 256>>>();
    out_kernel<<<dim3(16, 32), 128>>>(Wo, bo, out);
}

// round 4
// speedup vs baseline: 2.4885x; 1.0153x over previous
#include <cuda_runtime.h>
#include <math.h>
#include <stdint.h>

#define NTOK 2048

// ---------------- scratch ----------------
__device__ float g_q [(size_t)2 * 16 * NTOK * 64]; // [b][h][n][d]   (tf32, q pre-scaled)
__device__ float g_k [(size_t)2 * 4  * NTOK * 64]; // [b][kv][n][d]  (tf32)
__device__ float g_vt[(size_t)2 * 4  * 64 * NTOK]; // [b][kv][d][n]  (tf32, transposed)
__device__ float g_o [(size_t)4096 * 1024];        // [m][1024]      (tf32)

__device__ __forceinline__ float F2TF(float x) {
    uint32_t r; asm("cvt.rna.tf32.f32 %0, %1;" : "=r"(r) : "f"(x));
    return __uint_as_float(r);
}

__device__ __forceinline__ void mma8(float* d, float a0, float a1, float a2,
                                     float a3, float b0, float b1) {
    asm volatile(
        "mma.sync.aligned.m16n8k8.row.col.f32.tf32.tf32.f32 "
        "{%0,%1,%2,%3},{%4,%5,%6,%7},{%8,%9},{%0,%1,%2,%3};\n"
        : "+f"(d[0]), "+f"(d[1]), "+f"(d[2]), "+f"(d[3])
        : "r"(__float_as_uint(a0)), "r"(__float_as_uint(a1)),
          "r"(__float_as_uint(a2)), "r"(__float_as_uint(a3)),
          "r"(__float_as_uint(b0)), "r"(__float_as_uint(b1)));
}

#define CP_ASYNC16(dst, src) \
    asm volatile("cp.async.cg.shared.global [%0], [%1], 16;\n" :: "r"(dst), "l"(src))
#define CP_COMMIT() asm volatile("cp.async.commit_group;\n" ::: "memory")
#define CP_WAIT0()  asm volatile("cp.async.wait_group 0;\n" ::: "memory")

// =============================================================================
// Kernel 1: QKV GEMM + bias + RMSNorm + 3D RoPE + q-scale.
//   128 threads / 4 warps; warp tile 32x64; block 128x64. Register prefetch.
// =============================================================================
__global__ __launch_bounds__(128) void qkv_kernel(
    const float* __restrict__ x,
    const float* __restrict__ Wq, const float* __restrict__ bq,
    const float* __restrict__ Wk, const float* __restrict__ bk,
    const float* __restrict__ Wv, const float* __restrict__ bv,
    const float* __restrict__ qn, const float* __restrict__ kn)
{
    __shared__ float As[128 * 36];  // [m][k] pad 36
    __shared__ float Bt[64 * 34];   // [n][k] pad 34

    const int tid = threadIdx.x;
    const int w = tid >> 5, lane = tid & 31, g = lane >> 2, c = lane & 3;
    const int m0 = blockIdx.y * 128;
    const int colb = blockIdx.x * 64;

    const float* Bmat; const float* bias; int ldb, seg, colloc;
    if (colb < 1024)      { Bmat = Wq; bias = bq; ldb = 1024; seg = 0; colloc = colb; }
    else if (colb < 1280) { Bmat = Wk; bias = bk; ldb = 256;  seg = 1; colloc = colb - 1024; }
    else                  { Bmat = Wv; bias = bv; ldb = 256;  seg = 2; colloc = colb - 1280; }

    float acc[2][8][4] = {};
    const int ar = tid >> 3, ac4 = (tid & 7) * 4;   // A loader
    const int kr = tid >> 4, n4 = (tid & 15) * 4;   // B loader

    float4 aReg[8], bReg[4];
    #pragma unroll
    for (int p = 0; p < 8; p++)
        aReg[p] = *(const float4*)&x[(size_t)(m0 + p * 16 + ar) * 1024 + ac4];
    #pragma unroll
    for (int p = 0; p < 4; p++)
        bReg[p] = *(const float4*)&Bmat[(size_t)(p * 8 + kr) * ldb + colloc + n4];

    for (int k0 = 0; k0 < 1024; k0 += 32) {
        #pragma unroll
        for (int p = 0; p < 8; p++) {
            float* dst = &As[(p * 16 + ar) * 36 + ac4];
            dst[0] = F2TF(aReg[p].x); dst[1] = F2TF(aReg[p].y);
            dst[2] = F2TF(aReg[p].z); dst[3] = F2TF(aReg[p].w);
        }
        #pragma unroll
        for (int p = 0; p < 4; p++) {
            int k = p * 8 + kr;
            Bt[(n4 + 0) * 34 + k] = F2TF(bReg[p].x);
            Bt[(n4 + 1) * 34 + k] = F2TF(bReg[p].y);
            Bt[(n4 + 2) * 34 + k] = F2TF(bReg[p].z);
            Bt[(n4 + 3) * 34 + k] = F2TF(bReg[p].w);
        }
        __syncthreads();

        if (k0 + 32 < 1024) {   // prefetch next tile: LDG overlaps mma chain
            #pragma unroll
            for (int p = 0; p < 8; p++)
                aReg[p] = *(const float4*)&x[(size_t)(m0 + p * 16 + ar) * 1024 + k0 + 32 + ac4];
            #pragma unroll
            for (int p = 0; p < 4; p++)
                bReg[p] = *(const float4*)&Bmat[(size_t)(k0 + 32 + p * 8 + kr) * ldb + colloc + n4];
        }

        #pragma unroll
        for (int ks = 0; ks < 4; ks++) {
            float2 fa[4];
            #pragma unroll
            for (int r = 0; r < 4; r++)
                fa[r] = *(const float2*)&As[(w * 32 + r * 8 + g) * 36 + ks * 8 + 2 * c];
            #pragma unroll
            for (int nt = 0; nt < 8; nt++) {
                float2 wb = *(const float2*)&Bt[(nt * 8 + g) * 34 + ks * 8 + 2 * c];
                mma8(acc[0][nt], fa[0].x, fa[1].x, fa[0].y, fa[1].y, wb.x, wb.y);
                mma8(acc[1][nt], fa[2].x, fa[3].x, fa[2].y, fa[3].y, wb.x, wb.y);
            }
        }
        __syncthreads();
    }

    #pragma unroll
    for (int nt = 0; nt < 8; nt++) {
        float b0v = bias[colloc + nt * 8 + 2 * c];
        float b1v = bias[colloc + nt * 8 + 2 * c + 1];
        #pragma unroll
        for (int mt = 0; mt < 2; mt++) {
            acc[mt][nt][0] += b0v; acc[mt][nt][1] += b1v;
            acc[mt][nt][2] += b0v; acc[mt][nt][3] += b1v;
        }
    }

    const int head = colloc >> 6;

    if (seg == 2) {
        #pragma unroll
        for (int mt = 0; mt < 2; mt++) {
            int m_a = m0 + w * 32 + mt * 16 + g;
            int b_ = m_a >> 11, n0 = m_a & 2047, n1 = n0 + 8;
            float* vb = &g_vt[((size_t)(b_ * 4 + head)) * 64 * NTOK];
            #pragma unroll
            for (int nt = 0; nt < 8; nt++) {
                int d0 = nt * 8 + 2 * c;
                vb[(size_t)d0 * NTOK + n0]       = F2TF(acc[mt][nt][0]);
                vb[(size_t)(d0 + 1) * NTOK + n0] = F2TF(acc[mt][nt][1]);
                vb[(size_t)d0 * NTOK + n1]       = F2TF(acc[mt][nt][2]);
                vb[(size_t)(d0 + 1) * NTOK + n1] = F2TF(acc[mt][nt][3]);
            }
        }
        return;
    }

    // RMSNorm (intra-warp)
    const float* nw = (seg == 0) ? qn : kn;
    #pragma unroll
    for (int mt = 0; mt < 2; mt++) {
        float ss0 = 0.f, ss1 = 0.f;
        #pragma unroll
        for (int nt = 0; nt < 8; nt++) {
            ss0 += acc[mt][nt][0] * acc[mt][nt][0] + acc[mt][nt][1] * acc[mt][nt][1];
            ss1 += acc[mt][nt][2] * acc[mt][nt][2] + acc[mt][nt][3] * acc[mt][nt][3];
        }
        ss0 += __shfl_xor_sync(~0u, ss0, 1); ss0 += __shfl_xor_sync(~0u, ss0, 2);
        ss1 += __shfl_xor_sync(~0u, ss1, 1); ss1 += __shfl_xor_sync(~0u, ss1, 2);
        float rs0 = rsqrtf(ss0 * (1.f / 64.f) + 1e-6f);
        float rs1 = rsqrtf(ss1 * (1.f / 64.f) + 1e-6f);
        #pragma unroll
        for (int nt = 0; nt < 8; nt++) {
            float w0 = nw[nt * 8 + 2 * c], w1 = nw[nt * 8 + 2 * c + 1];
            acc[mt][nt][0] *= rs0 * w0; acc[mt][nt][1] *= rs0 * w1;
            acc[mt][nt][2] *= rs1 * w0; acc[mt][nt][3] *= rs1 * w1;
        }
    }

    // 3D RoPE in-place: pairs t:(0,1) h:(2,3) w:(4,6),(5,7)
    const int lo_[4] = {0, 2, 4, 5};
    const int hi_[4] = {1, 3, 6, 7};
    #pragma unroll
    for (int mt = 0; mt < 2; mt++) {
        int m_a = m0 + w * 32 + mt * 16 + g;
        int n0 = m_a & 2047, n1 = n0 + 8;
        float posr[2][3] = {
            {(float)(n0 >> 8), (float)((n0 >> 4) & 15), (float)(n0 & 15)},
            {(float)(n1 >> 8), (float)((n1 >> 4) & 15), (float)(n1 & 15)}};
        #pragma unroll
        for (int pi = 0; pi < 4; pi++) {
            int lo = lo_[pi], hi = hi_[pi];
            int ax = (pi == 0) ? 0 : (pi == 1 ? 1 : 2);
            float halfinv = (pi < 2) ? (1.f / 8.f) : (1.f / 16.f);
            #pragma unroll
            for (int e = 0; e < 2; e++) {
                float f = (pi < 2) ? (float)(2 * c + e)
                                   : (float)((lo & 1) * 8 + 2 * c + e);
                float inv = __powf(10000.f, -f * halfinv);
                #pragma unroll
                for (int r = 0; r < 2; r++) {
                    float sv, cv;
                    __sincosf(posr[r][ax] * inv, &sv, &cv);
                    float xl = acc[mt][lo][2 * r + e];
                    float xh = acc[mt][hi][2 * r + e];
                    acc[mt][lo][2 * r + e] = xl * cv - xh * sv;
                    acc[mt][hi][2 * r + e] = xh * cv + xl * sv;
                }
            }
        }
    }

    float scale = (seg == 0) ? 0.125f : 1.f;
    #pragma unroll
    for (int mt = 0; mt < 2; mt++) {
        int m_a = m0 + w * 32 + mt * 16 + g;
        int b_ = m_a >> 11, n0 = m_a & 2047, n1 = n0 + 8;
        float* qb = (seg == 0) ? &g_q[((size_t)(b_ * 16 + head)) * NTOK * 64]
                               : &g_k[((size_t)(b_ * 4 + head)) * NTOK * 64];
        #pragma unroll
        for (int nt = 0; nt < 8; nt++) {
            int d0 = nt * 8 + 2 * c;
            *(float2*)&qb[(size_t)n0 * 64 + d0] =
                make_float2(F2TF(acc[mt][nt][0] * scale), F2TF(acc[mt][nt][1] * scale));
            *(float2*)&qb[(size_t)n1 * 64 + d0] =
                make_float2(F2TF(acc[mt][nt][2] * scale), F2TF(acc[mt][nt][3] * scale));
        }
    }
}

// =============================================================================
// Kernel 2: flash attention without online max (scores bounded: |s|<=8 since
//   RMSNorm rows have L2 norm 8, RoPE orthogonal, 1/8 folded into q).
//   cp.async overlap: V(t) loads under S-compute, K(t+1) under PV-compute.
// =============================================================================
__global__ __launch_bounds__(256, 2) void attn_kernel()
{
    __shared__ float Ks[64 * 68];   // [key][d]
    __shared__ float Vs[64 * 68];   // [d][key]

    const int tid = threadIdx.x;
    const int w = tid >> 5, lane = tid & 31, g = lane >> 2, c = lane & 3;
    const int q0 = blockIdx.x * 128;
    const int bh = blockIdx.y;
    const int b_ = bh >> 4, h = bh & 15, kv = h >> 2;

    const float* qg = &g_q[((size_t)(b_ * 16 + h)) * NTOK * 64];
    const float* kg = &g_k[((size_t)(b_ * 4 + kv)) * NTOK * 64];
    const float* vg = &g_vt[((size_t)(b_ * 4 + kv)) * 64 * NTOK];

    const int lr = tid >> 2, lc = (tid & 3) * 16;
    const uint32_t ks_smem = (uint32_t)__cvta_generic_to_shared(&Ks[lr * 68 + lc]);
    const uint32_t vs_smem = (uint32_t)__cvta_generic_to_shared(&Vs[lr * 68 + lc]);

    // Q fragments register-resident
    float qf[8][4];
    {
        const float* r0 = &qg[(size_t)(q0 + w * 16 + g) * 64];
        const float* r1 = r0 + 8 * 64;
        #pragma unroll
        for (int ks = 0; ks < 8; ks++) {
            float2 a = *(const float2*)&r0[ks * 8 + 2 * c];
            float2 b = *(const float2*)&r1[ks * 8 + 2 * c];
            qf[ks][0] = a.x; qf[ks][1] = b.x; qf[ks][2] = a.y; qf[ks][3] = b.y;
        }
    }

    float o[8][4] = {};
    float lp0 = 0.f, lp1 = 0.f;   // per-thread partial row sums

    // prologue: K(0)
    #pragma unroll
    for (int i = 0; i < 4; i++)
        CP_ASYNC16(ks_smem + i * 16, &kg[(size_t)lr * 64 + lc + i * 4]);
    CP_COMMIT();

    for (int kt = 0; kt < NTOK; kt += 64) {
        CP_WAIT0();
        __syncthreads();        // K(t) visible; all PV(t-1) readers done with Vs

        // V(t) load overlaps S compute
        #pragma unroll
        for (int i = 0; i < 4; i++)
            CP_ASYNC16(vs_smem + i * 16, &vg[(size_t)lr * NTOK + kt + lc + i * 4]);
        CP_COMMIT();

        // S = Q K^T
        float s[8][4] = {};
        #pragma unroll
        for (int ks = 0; ks < 8; ks++) {
            #pragma unroll
            for (int nt = 0; nt < 8; nt++) {
                float2 kb = *(const float2*)&Ks[(nt * 8 + g) * 68 + ks * 8 + 2 * c];
                mma8(s[nt], qf[ks][0], qf[ks][1], qf[ks][2], qf[ks][3], kb.x, kb.y);
            }
        }

        // exp (no max shift: scores bounded) + partial sums
        #pragma unroll
        for (int nt = 0; nt < 8; nt++) {
            s[nt][0] = __expf(s[nt][0]); s[nt][1] = __expf(s[nt][1]);
            s[nt][2] = __expf(s[nt][2]); s[nt][3] = __expf(s[nt][3]);
            lp0 += s[nt][0] + s[nt][1];
            lp1 += s[nt][2] + s[nt][3];
        }

        CP_WAIT0();
        __syncthreads();        // V(t) visible; all S(t) readers done with Ks

        // K(t+1) load overlaps PV compute
        if (kt + 64 < NTOK) {
            #pragma unroll
            for (int i = 0; i < 4; i++)
                CP_ASYNC16(ks_smem + i * 16, &kg[(size_t)(kt + 64 + lr) * 64 + lc + i * 4]);
        }
        CP_COMMIT();

        // O += P V (S accumulator reused as A fragment)
        #pragma unroll
        for (int ks = 0; ks < 8; ks++) {
            float a0 = F2TF(s[ks][0]);
            float a1 = F2TF(s[ks][2]);
            float a2 = F2TF(s[ks][1]);
            float a3 = F2TF(s[ks][3]);
            #pragma unroll
            for (int nt = 0; nt < 8; nt++) {
                float2 vb = *(const float2*)&Vs[(nt * 8 + g) * 68 + ks * 8 + 2 * c];
                mma8(o[nt], a0, a1, a2, a3, vb.x, vb.y);
            }
        }
    }

    // final row-sum reduce (once, not per tile)
    lp0 += __shfl_xor_sync(~0u, lp0, 1); lp0 += __shfl_xor_sync(~0u, lp0, 2);
    lp1 += __shfl_xor_sync(~0u, lp1, 1); lp1 += __shfl_xor_sync(~0u, lp1, 2);
    float inv0 = 1.f / lp0, inv1 = 1.f / lp1;

    int n0 = q0 + w * 16 + g, n1 = n0 + 8;
    float* ob0 = &g_o[((size_t)(b_ * NTOK + n0)) * 1024 + h * 64];
    float* ob1 = &g_o[((size_t)(b_ * NTOK + n1)) * 1024 + h * 64];
    #pragma unroll
    for (int nt = 0; nt < 8; nt++) {
        int d0 = nt * 8 + 2 * c;
        *(float2*)&ob0[d0] = make_float2(F2TF(o[nt][0] * inv0), F2TF(o[nt][1] * inv0));
        *(float2*)&ob1[d0] = make_float2(F2TF(o[nt][2] * inv1), F2TF(o[nt][3] * inv1));
    }
}

// =============================================================================
// Kernel 3: out = O @ Wo + bo. Register prefetch.
// =============================================================================
__global__ __launch_bounds__(128) void out_kernel(
    const float* __restrict__ Wo, const float* __restrict__ bo,
    float* __restrict__ out)
{
    __shared__ float As[128 * 36];
    __shared__ float Bt[64 * 34];

    const int tid = threadIdx.x;
    const int w = tid >> 5, lane = tid & 31, g = lane >> 2, c = lane & 3;
    const int m0 = blockIdx.y * 128;
    const int colb = blockIdx.x * 64;

    float acc[2][8][4] = {};
    const int ar = tid >> 3, ac4 = (tid & 7) * 4;
    const int kr = tid >> 4, n4 = (tid & 15) * 4;

    float4 aReg[8], bReg[4];
    #pragma unroll
    for (int p = 0; p < 8; p++)
        aReg[p] = *(const float4*)&g_o[(size_t)(m0 + p * 16 + ar) * 1024 + ac4];
    #pragma unroll
    for (int p = 0; p < 4; p++)
        bReg[p] = *(const float4*)&Wo[(size_t)(p * 8 + kr) * 1024 + colb + n4];

    for (int k0 = 0; k0 < 1024; k0 += 32) {
        #pragma unroll
        for (int p = 0; p < 8; p++)
            *(float4*)&As[(p * 16 + ar) * 36 + ac4] = aReg[p];
        #pragma unroll
        for (int p = 0; p < 4; p++) {
            int k = p * 8 + kr;
            Bt[(n4 + 0) * 34 + k] = F2TF(bReg[p].x);
            Bt[(n4 + 1) * 34 + k] = F2TF(bReg[p].y);
            Bt[(n4 + 2) * 34 + k] = F2TF(bReg[p].z);
            Bt[(n4 + 3) * 34 + k] = F2TF(bReg[p].w);
        }
        __syncthreads();

        if (k0 + 32 < 1024) {
            #pragma unroll
            for (int p = 0; p < 8; p++)
                aReg[p] = *(const float4*)&g_o[(size_t)(m0 + p * 16 + ar) * 1024 + k0 + 32 + ac4];
            #pragma unroll
            for (int p = 0; p < 4; p++)
                bReg[p] = *(const float4*)&Wo[(size_t)(k0 + 32 + p * 8 + kr) * 1024 + colb + n4];
        }

        #pragma unroll
        for (int ks = 0; ks < 4; ks++) {
            float2 fa[4];
            #pragma unroll
            for (int r = 0; r < 4; r++)
                fa[r] = *(const float2*)&As[(w * 32 + r * 8 + g) * 36 + ks * 8 + 2 * c];
            #pragma unroll
            for (int nt = 0; nt < 8; nt++) {
                float2 wb = *(const float2*)&Bt[(nt * 8 + g) * 34 + ks * 8 + 2 * c];
                mma8(acc[0][nt], fa[0].x, fa[1].x, fa[0].y, fa[1].y, wb.x, wb.y);
                mma8(acc[1][nt], fa[2].x, fa[3].x, fa[2].y, fa[3].y, wb.x, wb.y);
            }
        }
        __syncthreads();
    }

    #pragma unroll
    for (int mt = 0; mt < 2; mt++) {
        int m_a = m0 + w * 32 + mt * 16 + g;
        float* r0 = &out[(size_t)m_a * 1024 + colb];
        float* r1 = &out[(size_t)(m_a + 8) * 1024 + colb];
        #pragma unroll
        for (int nt = 0; nt < 8; nt++) {
            int d0 = nt * 8 + 2 * c;
            float b0v = bo[colb + d0], b1v = bo[colb + d0 + 1];
            *(float2*)&r0[d0] = make_float2(acc[mt][nt][0] + b0v, acc[mt][nt][1] + b1v);
            *(float2*)&r1[d0] = make_float2(acc[mt][nt][2] + b0v, acc[mt][nt][3] + b1v);
        }
    }
}

// =============================================================================
extern "C" void kernel_launch(void* const* d_in, const int* in_sizes, int n_in,
                              void* d_out, int out_size)
{
    const float* x  = (const float*)d_in[0];
    const float* Wq = (const float*)d_in[1];
    const float* bq = (const float*)d_in[2];
    const float* Wk = (const float*)d_in[3];
    const float* bk = (const float*)d_in[4];
    const float* Wv = (const float*)d_in[5];
    const float* bv = (const float*)d_in[6];
    const float* Wo = (const float*)d_in[7];
    const float* bo = (const float*)d_in[8];
    const float* qn = (const float*)d_in[9];
    const float* kn = (const float*)d_in[10];
    float* out = (float*)d_out;

    qkv_kernel<<<dim3(24, 32), 128>>>(x, Wq, bq, Wk, bk, Wv, bv, qn, kn);
    attn_kernel<<<dim3(16, 32), 256>>>();
    out_kernel<<<dim3(16, 32), 128>>>(Wo, bo, out);
}

// round 6
// speedup vs baseline: 3.5224x; 1.4155x over previous
#include <cuda_runtime.h>
#include <math.h>
#include <stdint.h>

#define NTOK 2048

// ---------------- scratch (tf32-pre-rounded copies + intermediates) ----------
__device__ float g_xc [(size_t)4096 * 1024];       // x, tf32
__device__ float g_wqc[(size_t)1024 * 1024];       // Wq, tf32
__device__ float g_wkc[(size_t)1024 * 256];        // Wk, tf32
__device__ float g_wvc[(size_t)1024 * 256];        // Wv, tf32
__device__ float g_woc[(size_t)1024 * 1024];       // Wo, tf32
__device__ float g_q [(size_t)2 * 16 * NTOK * 64]; // [b][h][n][d]  tf32, q pre-scaled
__device__ float g_k [(size_t)2 * 4  * NTOK * 64]; // [b][kv][n][d] tf32
__device__ float g_vt[(size_t)2 * 4  * 64 * NTOK]; // [b][kv][d][n] tf32 (transposed)
__device__ float g_o [(size_t)4096 * 1024];        // [m][1024]     tf32

__device__ __forceinline__ float F2TF(float x) {
    uint32_t r; asm("cvt.rna.tf32.f32 %0, %1;" : "=r"(r) : "f"(x));
    return __uint_as_float(r);
}

__device__ __forceinline__ void mma8(float* d, float a0, float a1, float a2,
                                     float a3, float b0, float b1) {
    asm volatile(
        "mma.sync.aligned.m16n8k8.row.col.f32.tf32.tf32.f32 "
        "{%0,%1,%2,%3},{%4,%5,%6,%7},{%8,%9},{%0,%1,%2,%3};\n"
        : "+f"(d[0]), "+f"(d[1]), "+f"(d[2]), "+f"(d[3])
        : "r"(__float_as_uint(a0)), "r"(__float_as_uint(a1)),
          "r"(__float_as_uint(a2)), "r"(__float_as_uint(a3)),
          "r"(__float_as_uint(b0)), "r"(__float_as_uint(b1)));
}

#define CP_ASYNC16(dst, src) \
    asm volatile("cp.async.cg.shared.global [%0], [%1], 16;\n" :: "r"(dst), "l"(src))
#define CP_COMMIT() asm volatile("cp.async.commit_group;\n" ::: "memory")
#define CP_WAIT0()  asm volatile("cp.async.wait_group 0;\n" ::: "memory")
#define CP_WAIT1()  asm volatile("cp.async.wait_group 1;\n" ::: "memory")

// =============================================================================
// Kernel 0: one-shot tf32 pre-conversion of x and weights
// =============================================================================
#define C_X  1048576
#define C_WQ (C_X + 262144)
#define C_WK (C_WQ + 65536)
#define C_WV (C_WK + 65536)
#define C_WO (C_WV + 262144)   // 1703936 float4s total

__global__ __launch_bounds__(256) void cvt_kernel(
    const float4* __restrict__ x,  const float4* __restrict__ wq,
    const float4* __restrict__ wk, const float4* __restrict__ wv,
    const float4* __restrict__ wo)
{
    int i = blockIdx.x * 256 + threadIdx.x;
    if (i >= C_WO) return;
    const float4* src; float4* dst; int off;
    if (i < C_X)       { src = x;  dst = (float4*)g_xc;  off = i; }
    else if (i < C_WQ) { src = wq; dst = (float4*)g_wqc; off = i - C_X; }
    else if (i < C_WK) { src = wk; dst = (float4*)g_wkc; off = i - C_WQ; }
    else if (i < C_WV) { src = wv; dst = (float4*)g_wvc; off = i - C_WK; }
    else               { src = wo; dst = (float4*)g_woc; off = i - C_WV; }
    float4 v = src[off];
    dst[off] = make_float4(F2TF(v.x), F2TF(v.y), F2TF(v.z), F2TF(v.w));
}

// =============================================================================
// GEMM mainloop core (shared by qkv/out): 128 threads, 4 warps, tile 128x64,
// k-step 32, 2-stage cp.async double buffer. A[m][k] pad36, B[k][n] pad68.
// =============================================================================
#define A_SZ (128 * 36)
#define B_SZ (32 * 68)
#define GEMM_SMEM ((2 * A_SZ + 2 * B_SZ) * 4)

__device__ __forceinline__ void gemm_mainloop(
    const float* __restrict__ Amat, size_t lda,
    const float* __restrict__ Bmat, size_t ldb, int colloc,
    float* sm, int tid, int w, int g, int c, int m0,
    float acc[2][8][4])
{
    float* As = sm;
    float* Bs = sm + 2 * A_SZ;
    const uint32_t as_u = (uint32_t)__cvta_generic_to_shared(As);
    const uint32_t bs_u = (uint32_t)__cvta_generic_to_shared(Bs);

    const int aRow = tid >> 3, aCol = (tid & 7) * 4;   // 16 rows x 8 thr, 8 reps
    const int bRow = tid >> 4, bCol = (tid & 15) * 4;  // 8 rows x 16 thr, 4 reps

    // prologue: stage 0
    {
        #pragma unroll
        for (int p = 0; p < 8; p++)
            CP_ASYNC16(as_u + ((p * 16 + aRow) * 36 + aCol) * 4,
                       &Amat[(size_t)(m0 + p * 16 + aRow) * lda + aCol]);
        #pragma unroll
        for (int p = 0; p < 4; p++)
            CP_ASYNC16(bs_u + ((p * 8 + bRow) * 68 + bCol) * 4,
                       &Bmat[(size_t)(p * 8 + bRow) * ldb + colloc + bCol]);
        CP_COMMIT();
    }

    for (int i = 0; i < 32; i++) {
        const int cur = i & 1;
        if (i + 1 < 32) {
            const int nxt = 1 - cur;
            const int k0 = (i + 1) * 32;
            #pragma unroll
            for (int p = 0; p < 8; p++)
                CP_ASYNC16(as_u + (nxt * A_SZ + (p * 16 + aRow) * 36 + aCol) * 4,
                           &Amat[(size_t)(m0 + p * 16 + aRow) * lda + k0 + aCol]);
            #pragma unroll
            for (int p = 0; p < 4; p++)
                CP_ASYNC16(bs_u + (nxt * B_SZ + (p * 8 + bRow) * 68 + bCol) * 4,
                           &Bmat[(size_t)(k0 + p * 8 + bRow) * ldb + colloc + bCol]);
            CP_COMMIT();
            CP_WAIT1();
        } else {
            CP_WAIT0();
        }
        __syncthreads();

        const float* Ac = As + cur * A_SZ;
        const float* Bc = Bs + cur * B_SZ;
        #pragma unroll
        for (int ks = 0; ks < 4; ks++) {
            float2 fa[4];
            #pragma unroll
            for (int r = 0; r < 4; r++)
                fa[r] = *(const float2*)&Ac[(w * 32 + r * 8 + g) * 36 + ks * 8 + 2 * c];
            #pragma unroll
            for (int nt = 0; nt < 8; nt++) {
                float b0 = Bc[(ks * 8 + 2 * c) * 68 + nt * 8 + g];
                float b1 = Bc[(ks * 8 + 2 * c + 1) * 68 + nt * 8 + g];
                mma8(acc[0][nt], fa[0].x, fa[1].x, fa[0].y, fa[1].y, b0, b1);
                mma8(acc[1][nt], fa[2].x, fa[3].x, fa[2].y, fa[3].y, b0, b1);
            }
        }
        __syncthreads();
    }
}

// =============================================================================
// Kernel 1: QKV GEMM + bias + RMSNorm + 3D RoPE + q-scale
// =============================================================================
__global__ __launch_bounds__(128) void qkv_kernel(
    const float* __restrict__ bq, const float* __restrict__ bk,
    const float* __restrict__ bv,
    const float* __restrict__ qn, const float* __restrict__ kn)
{
    extern __shared__ float sm[];
    const int tid = threadIdx.x;
    const int w = tid >> 5, lane = tid & 31, g = lane >> 2, c = lane & 3;
    const int m0 = blockIdx.y * 128;
    const int colb = blockIdx.x * 64;

    const float* Bmat; const float* bias; int ldb, seg, colloc;
    if (colb < 1024)      { Bmat = g_wqc; bias = bq; ldb = 1024; seg = 0; colloc = colb; }
    else if (colb < 1280) { Bmat = g_wkc; bias = bk; ldb = 256;  seg = 1; colloc = colb - 1024; }
    else                  { Bmat = g_wvc; bias = bv; ldb = 256;  seg = 2; colloc = colb - 1280; }

    float acc[2][8][4] = {};
    gemm_mainloop(g_xc, 1024, Bmat, ldb, colloc, sm, tid, w, g, c, m0, acc);

    #pragma unroll
    for (int nt = 0; nt < 8; nt++) {
        float b0v = bias[colloc + nt * 8 + 2 * c];
        float b1v = bias[colloc + nt * 8 + 2 * c + 1];
        #pragma unroll
        for (int mt = 0; mt < 2; mt++) {
            acc[mt][nt][0] += b0v; acc[mt][nt][1] += b1v;
            acc[mt][nt][2] += b0v; acc[mt][nt][3] += b1v;
        }
    }

    const int head = colloc >> 6;

    if (seg == 2) {
        #pragma unroll
        for (int mt = 0; mt < 2; mt++) {
            int m_a = m0 + w * 32 + mt * 16 + g;
            int b_ = m_a >> 11, n0 = m_a & 2047, n1 = n0 + 8;
            float* vb = &g_vt[((size_t)(b_ * 4 + head)) * 64 * NTOK];
            #pragma unroll
            for (int nt = 0; nt < 8; nt++) {
                int d0 = nt * 8 + 2 * c;
                vb[(size_t)d0 * NTOK + n0]       = F2TF(acc[mt][nt][0]);
                vb[(size_t)(d0 + 1) * NTOK + n0] = F2TF(acc[mt][nt][1]);
                vb[(size_t)d0 * NTOK + n1]       = F2TF(acc[mt][nt][2]);
                vb[(size_t)(d0 + 1) * NTOK + n1] = F2TF(acc[mt][nt][3]);
            }
        }
        return;
    }

    // RMSNorm (intra-warp over 64-wide head dim)
    const float* nw = (seg == 0) ? qn : kn;
    #pragma unroll
    for (int mt = 0; mt < 2; mt++) {
        float ss0 = 0.f, ss1 = 0.f;
        #pragma unroll
        for (int nt = 0; nt < 8; nt++) {
            ss0 += acc[mt][nt][0] * acc[mt][nt][0] + acc[mt][nt][1] * acc[mt][nt][1];
            ss1 += acc[mt][nt][2] * acc[mt][nt][2] + acc[mt][nt][3] * acc[mt][nt][3];
        }
        ss0 += __shfl_xor_sync(~0u, ss0, 1); ss0 += __shfl_xor_sync(~0u, ss0, 2);
        ss1 += __shfl_xor_sync(~0u, ss1, 1); ss1 += __shfl_xor_sync(~0u, ss1, 2);
        float rs0 = rsqrtf(ss0 * (1.f / 64.f) + 1e-6f);
        float rs1 = rsqrtf(ss1 * (1.f / 64.f) + 1e-6f);
        #pragma unroll
        for (int nt = 0; nt < 8; nt++) {
            float w0 = nw[nt * 8 + 2 * c], w1 = nw[nt * 8 + 2 * c + 1];
            acc[mt][nt][0] *= rs0 * w0; acc[mt][nt][1] *= rs0 * w1;
            acc[mt][nt][2] *= rs1 * w0; acc[mt][nt][3] *= rs1 * w1;
        }
    }

    // 3D RoPE in-place: pairs t:(0,1) h:(2,3) w:(4,6),(5,7)
    const int lo_[4] = {0, 2, 4, 5};
    const int hi_[4] = {1, 3, 6, 7};
    #pragma unroll
    for (int mt = 0; mt < 2; mt++) {
        int m_a = m0 + w * 32 + mt * 16 + g;
        int n0 = m_a & 2047, n1 = n0 + 8;
        float posr[2][3] = {
            {(float)(n0 >> 8), (float)((n0 >> 4) & 15), (float)(n0 & 15)},
            {(float)(n1 >> 8), (float)((n1 >> 4) & 15), (float)(n1 & 15)}};
        #pragma unroll
        for (int pi = 0; pi < 4; pi++) {
            int lo = lo_[pi], hi = hi_[pi];
            int ax = (pi == 0) ? 0 : (pi == 1 ? 1 : 2);
            float halfinv = (pi < 2) ? (1.f / 8.f) : (1.f / 16.f);
            #pragma unroll
            for (int e = 0; e < 2; e++) {
                float f = (pi < 2) ? (float)(2 * c + e)
                                   : (float)((lo & 1) * 8 + 2 * c + e);
                float inv = __powf(10000.f, -f * halfinv);
                #pragma unroll
                for (int r = 0; r < 2; r++) {
                    float sv, cv;
                    __sincosf(posr[r][ax] * inv, &sv, &cv);
                    float xl = acc[mt][lo][2 * r + e];
                    float xh = acc[mt][hi][2 * r + e];
                    acc[mt][lo][2 * r + e] = xl * cv - xh * sv;
                    acc[mt][hi][2 * r + e] = xh * cv + xl * sv;
                }
            }
        }
    }

    float scale = (seg == 0) ? 0.125f : 1.f;
    #pragma unroll
    for (int mt = 0; mt < 2; mt++) {
        int m_a = m0 + w * 32 + mt * 16 + g;
        int b_ = m_a >> 11, n0 = m_a & 2047, n1 = n0 + 8;
        float* qb = (seg == 0) ? &g_q[((size_t)(b_ * 16 + head)) * NTOK * 64]
                               : &g_k[((size_t)(b_ * 4 + head)) * NTOK * 64];
        #pragma unroll
        for (int nt = 0; nt < 8; nt++) {
            int d0 = nt * 8 + 2 * c;
            *(float2*)&qb[(size_t)n0 * 64 + d0] =
                make_float2(F2TF(acc[mt][nt][0] * scale), F2TF(acc[mt][nt][1] * scale));
            *(float2*)&qb[(size_t)n1 * 64 + d0] =
                make_float2(F2TF(acc[mt][nt][2] * scale), F2TF(acc[mt][nt][3] * scale));
        }
    }
}

// =============================================================================
// Kernel 2: flash attention, no online max (scores bounded |s|<=8).
//   128 threads / 4 warps; warp M=32; Q register-resident; split cp.async.
// =============================================================================
__global__ __launch_bounds__(128) void attn_kernel()
{
    __shared__ float Ks[64 * 68];   // [key][d]
    __shared__ float Vs[64 * 68];   // [d][key]

    const int tid = threadIdx.x;
    const int w = tid >> 5, lane = tid & 31, g = lane >> 2, c = lane & 3;
    const int q0 = blockIdx.x * 128;
    const int bh = blockIdx.y;
    const int b_ = bh >> 4, h = bh & 15, kv = h >> 2;

    const float* qg = &g_q[((size_t)(b_ * 16 + h)) * NTOK * 64];
    const float* kg = &g_k[((size_t)(b_ * 4 + kv)) * NTOK * 64];
    const float* vg = &g_vt[((size_t)(b_ * 4 + kv)) * 64 * NTOK];

    const int lr = tid >> 1, lc = (tid & 1) * 32;
    const uint32_t ks_u = (uint32_t)__cvta_generic_to_shared(&Ks[lr * 68 + lc]);
    const uint32_t vs_u = (uint32_t)__cvta_generic_to_shared(&Vs[lr * 68 + lc]);

    // Q fragments register-resident
    float qf[2][8][4];
    {
        const float* r0 = &qg[(size_t)(q0 + w * 32 + g) * 64];
        #pragma unroll
        for (int ks = 0; ks < 8; ks++) {
            float2 a = *(const float2*)&r0[ks * 8 + 2 * c];
            float2 b = *(const float2*)&r0[8 * 64 + ks * 8 + 2 * c];
            float2 d = *(const float2*)&r0[16 * 64 + ks * 8 + 2 * c];
            float2 e = *(const float2*)&r0[24 * 64 + ks * 8 + 2 * c];
            qf[0][ks][0] = a.x; qf[0][ks][1] = b.x; qf[0][ks][2] = a.y; qf[0][ks][3] = b.y;
            qf[1][ks][0] = d.x; qf[1][ks][1] = e.x; qf[1][ks][2] = d.y; qf[1][ks][3] = e.y;
        }
    }

    float o[2][8][4] = {};
    float lp[4] = {0.f, 0.f, 0.f, 0.f};

    #pragma unroll
    for (int i = 0; i < 8; i++)
        CP_ASYNC16(ks_u + i * 16, &kg[(size_t)lr * 64 + lc + i * 4]);
    CP_COMMIT();

    for (int kt = 0; kt < NTOK; kt += 64) {
        CP_WAIT0();
        __syncthreads();

        #pragma unroll
        for (int i = 0; i < 8; i++)
            CP_ASYNC16(vs_u + i * 16, &vg[(size_t)lr * NTOK + kt + lc + i * 4]);
        CP_COMMIT();

        // S = Q K^T
        float s[2][8][4] = {};
        #pragma unroll
        for (int ks = 0; ks < 8; ks++) {
            #pragma unroll
            for (int nt = 0; nt < 8; nt++) {
                float2 kb = *(const float2*)&Ks[(nt * 8 + g) * 68 + ks * 8 + 2 * c];
                mma8(s[0][nt], qf[0][ks][0], qf[0][ks][1], qf[0][ks][2], qf[0][ks][3], kb.x, kb.y);
                mma8(s[1][nt], qf[1][ks][0], qf[1][ks][1], qf[1][ks][2], qf[1][ks][3], kb.x, kb.y);
            }
        }

        #pragma unroll
        for (int mt = 0; mt < 2; mt++)
            #pragma unroll
            for (int nt = 0; nt < 8; nt++) {
                s[mt][nt][0] = __expf(s[mt][nt][0]); s[mt][nt][1] = __expf(s[mt][nt][1]);
                s[mt][nt][2] = __expf(s[mt][nt][2]); s[mt][nt][3] = __expf(s[mt][nt][3]);
                lp[2 * mt]     += s[mt][nt][0] + s[mt][nt][1];
                lp[2 * mt + 1] += s[mt][nt][2] + s[mt][nt][3];
            }

        CP_WAIT0();
        __syncthreads();

        if (kt + 64 < NTOK) {
            #pragma unroll
            for (int i = 0; i < 8; i++)
                CP_ASYNC16(ks_u + i * 16, &kg[(size_t)(kt + 64 + lr) * 64 + lc + i * 4]);
            CP_COMMIT();
        }

        // O += P V
        #pragma unroll
        for (int ks = 0; ks < 8; ks++) {
            float a00 = F2TF(s[0][ks][0]), a01 = F2TF(s[0][ks][2]);
            float a02 = F2TF(s[0][ks][1]), a03 = F2TF(s[0][ks][3]);
            float a10 = F2TF(s[1][ks][0]), a11 = F2TF(s[1][ks][2]);
            float a12 = F2TF(s[1][ks][1]), a13 = F2TF(s[1][ks][3]);
            #pragma unroll
            for (int nt = 0; nt < 8; nt++) {
                float2 vb = *(const float2*)&Vs[(nt * 8 + g) * 68 + ks * 8 + 2 * c];
                mma8(o[0][nt], a00, a01, a02, a03, vb.x, vb.y);
                mma8(o[1][nt], a10, a11, a12, a13, vb.x, vb.y);
            }
        }
    }

    #pragma unroll
    for (int i = 0; i < 4; i++) {
        lp[i] += __shfl_xor_sync(~0u, lp[i], 1);
        lp[i] += __shfl_xor_sync(~0u, lp[i], 2);
    }

    #pragma unroll
    for (int mt = 0; mt < 2; mt++) {
        float inv0 = 1.f / lp[2 * mt], inv1 = 1.f / lp[2 * mt + 1];
        int n0 = q0 + w * 32 + mt * 16 + g, n1 = n0 + 8;
        float* ob0 = &g_o[((size_t)(b_ * NTOK + n0)) * 1024 + h * 64];
        float* ob1 = &g_o[((size_t)(b_ * NTOK + n1)) * 1024 + h * 64];
        #pragma unroll
        for (int nt = 0; nt < 8; nt++) {
            int d0 = nt * 8 + 2 * c;
            *(float2*)&ob0[d0] = make_float2(F2TF(o[mt][nt][0] * inv0), F2TF(o[mt][nt][1] * inv0));
            *(float2*)&ob1[d0] = make_float2(F2TF(o[mt][nt][2] * inv1), F2TF(o[mt][nt][3] * inv1));
        }
    }
}

// =============================================================================
// Kernel 3: out = O @ Wo + bo
// =============================================================================
__global__ __launch_bounds__(128) void out_kernel(
    const float* __restrict__ bo, float* __restrict__ out)
{
    extern __shared__ float sm[];
    const int tid = threadIdx.x;
    const int w = tid >> 5, lane = tid & 31, g = lane >> 2, c = lane & 3;
    const int m0 = blockIdx.y * 128;
    const int colb = blockIdx.x * 64;

    float acc[2][8][4] = {};
    gemm_mainloop(g_o, 1024, g_woc, 1024, colb, sm, tid, w, g, c, m0, acc);

    #pragma unroll
    for (int mt = 0; mt < 2; mt++) {
        int m_a = m0 + w * 32 + mt * 16 + g;
        float* r0 = &out[(size_t)m_a * 1024 + colb];
        float* r1 = &out[(size_t)(m_a + 8) * 1024 + colb];
        #pragma unroll
        for (int nt = 0; nt < 8; nt++) {
            int d0 = nt * 8 + 2 * c;
            float b0v = bo[colb + d0], b1v = bo[colb + d0 + 1];
            *(float2*)&r0[d0] = make_float2(acc[mt][nt][0] + b0v, acc[mt][nt][1] + b1v);
            *(float2*)&r1[d0] = make_float2(acc[mt][nt][2] + b0v, acc[mt][nt][3] + b1v);
        }
    }
}

// =============================================================================
extern "C" void kernel_launch(void* const* d_in, const int* in_sizes, int n_in,
                              void* d_out, int out_size)
{
    const float* x  = (const float*)d_in[0];
    const float* Wq = (const float*)d_in[1];
    const float* bq = (const float*)d_in[2];
    const float* Wk = (const float*)d_in[3];
    const float* bk = (const float*)d_in[4];
    const float* Wv = (const float*)d_in[5];
    const float* bv = (const float*)d_in[6];
    const float* Wo = (const float*)d_in[7];
    const float* bo = (const float*)d_in[8];
    const float* qn = (const float*)d_in[9];
    const float* kn = (const float*)d_in[10];
    float* out = (float*)d_out;

    cudaFuncSetAttribute(qkv_kernel, cudaFuncAttributeMaxDynamicSharedMemorySize, GEMM_SMEM);
    cudaFuncSetAttribute(out_kernel, cudaFuncAttributeMaxDynamicSharedMemorySize, GEMM_SMEM);

    cvt_kernel<<<(C_WO + 255) / 256, 256>>>(
        (const float4*)x, (const float4*)Wq, (const float4*)Wk,
        (const float4*)Wv, (const float4*)Wo);
    qkv_kernel<<<dim3(24, 32), 128, GEMM_SMEM>>>(bq, bk, bv, qn, kn);
    attn_kernel<<<dim3(16, 32), 128>>>();
    out_kernel<<<dim3(16, 32), 128, GEMM_SMEM>>>(bo, out);
}